// round 14
// baseline (speedup 1.0000x reference)
#include <cuda_runtime.h>
#include <cuda_fp16.h>

// ---------------- problem constants ----------------
#define NB   2
#define CR_  256
#define CS_  512
#define LL   4096     // 64*64
#define PS_  1024     // 32*32
#define DI_  512
#define DS_  16
#define NCH  32       // scan chunks
#define CT_  128      // chunk length (NCH*CT_ == LL)
#define TT_  (NB*DI_*DS_)   // 16384 scan tracks
#define EPSF 1e-5f
#define LOG2E 1.4426950408889634f

__device__ __forceinline__ unsigned tf32c(float x) {
    unsigned r; asm("cvt.rna.tf32.f32 %0, %1;" : "=r"(r) : "f"(x)); return r;
}
__device__ __forceinline__ void mma8(float* c, const unsigned* a, const unsigned* b) {
    asm volatile("mma.sync.aligned.m16n8k8.row.col.f32.tf32.tf32.f32 "
        "{%0,%1,%2,%3}, {%4,%5,%6,%7}, {%8,%9}, {%0,%1,%2,%3};"
        : "+f"(c[0]), "+f"(c[1]), "+f"(c[2]), "+f"(c[3])
        : "r"(a[0]), "r"(a[1]), "r"(a[2]), "r"(a[3]), "r"(b[0]), "r"(b[1]));
}

// ---------------- scratch (static device allocs only) ----------------
__device__ float   g_sp   [NB*CR_*PS_];
__device__ float   g_fused[NB*CR_*LL];
__device__ __half  g_xth  [NB*LL*CR_];    // fused transposed, fp16
__device__ float2  g_psum [NB*LL*8];
__device__ __half  g_xmh  [NB*LL*DI_];    // xm fp16
__device__ __half  g_zh   [NB*LL*DI_];    // z fp16
__device__ __half  g_uh   [NB*LL*DI_];    // u fp16
__device__ float   g_dtin [NB*LL*DS_];
__device__ float2  g_bcc  [NB*LL*DS_];    // {B_s, C_s} fp32 interleaved
__device__ __half2 g_a    [NB*LL*DI_];    // {dt, dt*u} fp16
__device__ __half2 g_uz   [NB*LL*DI_];    // {u, silu(z)} fp16
__device__ float   g_P    [NCH*TT_];      // chunk-major, state-pairs contiguous
__device__ float   g_Hc   [NCH*TT_];
__device__ float   g_hini [NCH*TT_];      // materialized chunk-prefix states
__device__ __half  g_yfin [NB*LL*DI_];    // y fp16

// =====================================================================
// K1: scp 1x1 conv GEMM + BN — TF32 TC, 64x64 tiles (full-wave grid)
// =====================================================================
__global__ void __launch_bounds__(256)
k_scp_tc(const float* __restrict__ scp, const float* __restrict__ w,
         const float* __restrict__ gg, const float* __restrict__ bb,
         const float* __restrict__ mm, const float* __restrict__ vv) {
    __shared__ __align__(16) unsigned As[64 * 36];   // W  [o][k]
    __shared__ __align__(16) unsigned Bs[64 * 33];   // scp^T [p][k]
    const int b  = blockIdx.z;
    const int m0 = blockIdx.x * 64;   // o
    const int n0 = blockIdx.y * 64;   // p
    const int tid = threadIdx.x, lane = tid & 31, wid = tid >> 5;
    const int wm = wid >> 1, wn = wid & 1;        // 4 x 2 warps
    const int g = lane >> 2, t4 = lane & 3;
    const int r0 = tid >> 2, q8 = (tid & 3) * 8;  // 64 rows x 8 cols
    const int kq8 = tid >> 5, p2 = (tid & 31) * 2;
    float acc[4][4] = {};
    for (int st = 0; st < 16; st++) {
        const int k0 = st * 32;
        // A: W[o][k] 64x32
        float4 a0 = *(const float4*)&w[(m0 + r0) * 512 + k0 + q8];
        float4 a1 = *(const float4*)&w[(m0 + r0) * 512 + k0 + q8 + 4];
        unsigned* da = &As[r0 * 36 + q8];
        da[0] = tf32c(a0.x); da[1] = tf32c(a0.y); da[2] = tf32c(a0.z); da[3] = tf32c(a0.w);
        da[4] = tf32c(a1.x); da[5] = tf32c(a1.y); da[6] = tf32c(a1.z); da[7] = tf32c(a1.w);
        // B: scp^T transpose-stage 32k x 64p
#pragma unroll
        for (int j = 0; j < 4; j++) {
            int kk = j * 8 + kq8;
            float2 v = *(const float2*)&scp[(b * 512 + k0 + kk) * 1024 + n0 + p2];
            Bs[p2 * 33 + kk]       = tf32c(v.x);
            Bs[(p2 + 1) * 33 + kk] = tf32c(v.y);
        }
        __syncthreads();
#pragma unroll
        for (int k8 = 0; k8 < 4; k8++) {
            const int kb = k8 * 8;
            unsigned af[4], bf[4][2];
            {
                int m = wm * 16 + g;
                af[0] = As[m * 36 + kb + t4];
                af[1] = As[(m + 8) * 36 + kb + t4];
                af[2] = As[m * 36 + kb + t4 + 4];
                af[3] = As[(m + 8) * 36 + kb + t4 + 4];
            }
#pragma unroll
            for (int nf = 0; nf < 4; nf++) {
                int n = wn * 32 + nf * 8 + g;
                bf[nf][0] = Bs[n * 33 + kb + t4];
                bf[nf][1] = Bs[n * 33 + kb + t4 + 4];
            }
#pragma unroll
            for (int nf = 0; nf < 4; nf++)
                mma8(acc[nf], af, bf[nf]);
        }
        __syncthreads();
    }
    {
        int o = m0 + wm * 16 + g;
        float iv0 = gg[o] * rsqrtf(vv[o] + EPSF);
        float be0 = bb[o] - mm[o] * iv0;
        float iv1 = gg[o + 8] * rsqrtf(vv[o + 8] + EPSF);
        float be1 = bb[o + 8] - mm[o + 8] * iv1;
#pragma unroll
        for (int nf = 0; nf < 4; nf++) {
            int p = n0 + wn * 32 + nf * 8 + 2 * t4;
            float* dp  = &g_sp[(b * 256 + o) * 1024 + p];
            float* dp8 = &g_sp[(b * 256 + o + 8) * 1024 + p];
            dp[0]  = acc[nf][0] * iv0 + be0;
            dp[1]  = acc[nf][1] * iv0 + be0;
            dp8[0] = acc[nf][2] * iv1 + be1;
            dp8[1] = acc[nf][3] * iv1 + be1;
        }
    }
}

// =====================================================================
// K2: fused = BN(resnet) + bilinear(sp); (B,C,HW) fp32 + (B,HW,C) fp16
//     + LN psums
// =====================================================================
__global__ void k_fuse(const float* __restrict__ res,
                       const float* __restrict__ rg, const float* __restrict__ rb,
                       const float* __restrict__ rm, const float* __restrict__ rv) {
    __shared__ float tile[32][33];
    const int b  = blockIdx.z;
    const int c0 = blockIdx.y * 32;
    const int l0 = blockIdx.x * 32;
    const int tx = threadIdx.x, ty = threadIdx.y;
    const int l = l0 + tx;
    const int h = l >> 6, wq = l & 63;
    float sh = h * 0.5f - 0.25f;
    float sw = wq * 0.5f - 0.25f;
    int h0 = (int)floorf(sh); float fh = sh - (float)h0;
    int w0 = (int)floorf(sw); float fw = sw - (float)w0;
    int h0c = max(h0, 0), h1c = min(h0 + 1, 31);
    int w0c = max(w0, 0), w1c = min(w0 + 1, 31);
#pragma unroll
    for (int i = 0; i < 4; i++) {
        int c = c0 + ty + i * 8;
        float inv  = rg[c] * rsqrtf(rv[c] + EPSF);
        float beta = rb[c] - rm[c] * inv;
        float val = res[(b * 256 + c) * 4096 + l] * inv + beta;
        const float* spb = g_sp + (b * 256 + c) * 1024;
        float s00 = spb[h0c * 32 + w0c], s01 = spb[h0c * 32 + w1c];
        float s10 = spb[h1c * 32 + w0c], s11 = spb[h1c * 32 + w1c];
        val += (1.f - fh) * ((1.f - fw) * s00 + fw * s01)
             +        fh  * ((1.f - fw) * s10 + fw * s11);
        g_fused[(b * 256 + c) * 4096 + l] = val;
        tile[ty + i * 8][tx] = val;
    }
    __syncthreads();
#pragma unroll
    for (int i = 0; i < 4; i++) {
        int c  = c0 + tx;
        int ll = l0 + ty + i * 8;
        g_xth[(b * 4096 + ll) * 256 + c] = __float2half(tile[tx][ty + i * 8]);
    }
    const int tid = ty * 32 + tx;
    if (tid < 32) {
        float s = 0.f, q = 0.f;
#pragma unroll
        for (int cc = 0; cc < 32; cc++) {
            float v = tile[cc][tid];
            s += v; q += v * v;
        }
        g_psum[(b * 4096 + l0 + tid) * 8 + (c0 >> 5)] = make_float2(s, q);
    }
}

// =====================================================================
// K4: in_proj GEMM — TF32 TC, fp16 A source, double-buffered, fused LN
// =====================================================================
__global__ void __launch_bounds__(256)
k_inproj_tc(const float* __restrict__ w,
            const float* __restrict__ lg, const float* __restrict__ lb) {
    extern __shared__ unsigned dyn[];
    unsigned* As = dyn;             // [2][128*36]
    unsigned* Bs = dyn + 2 * 4608;  // [2][128*36]
    __shared__ float s_mu[128], s_rs[128];
    const int m0 = blockIdx.x * 128, n0 = blockIdx.y * 128;
    const int tid = threadIdx.x, lane = tid & 31, wid = tid >> 5;
    const int wm = wid >> 2, wn = wid & 3;
    const int g = lane >> 2, t4 = lane & 3;
    if (tid < 128) {
        float s = 0.f, qq = 0.f;
#pragma unroll
        for (int i = 0; i < 8; i++) {
            float2 p = g_psum[(m0 + tid) * 8 + i];
            s += p.x; qq += p.y;
        }
        float mu = s * (1.f / 256.f);
        s_mu[tid] = mu;
        s_rs[tid] = rsqrtf(qq * (1.f / 256.f) - mu * mu + EPSF);
    }
    __syncthreads();
    const int r0 = tid >> 3, c4 = tid & 7;
    float mu[4], rs[4];
#pragma unroll
    for (int i = 0; i < 4; i++) { mu[i] = s_mu[r0 + 32 * i]; rs[i] = s_rs[r0 + 32 * i]; }
    float acc[4][4][4] = {};
    uint2 ahx[4]; float4 bv[4], g4, e4;
#pragma unroll
    for (int i = 0; i < 4; i++) {
        ahx[i] = *(const uint2*)&g_xth[(m0 + r0 + 32 * i) * 256 + c4 * 4];
        bv[i]  = *(const float4*)&w[(n0 + r0 + 32 * i) * 256 + c4 * 4];
    }
    g4 = *(const float4*)&lg[c4 * 4];
    e4 = *(const float4*)&lb[c4 * 4];
#pragma unroll
    for (int i = 0; i < 4; i++) {
        int row = r0 + 32 * i;
        float2 f01 = __half22float2(*(const __half2*)&ahx[i].x);
        float2 f23 = __half22float2(*(const __half2*)&ahx[i].y);
        unsigned* da = &As[row * 36 + c4 * 4];
        da[0] = tf32c((f01.x - mu[i]) * rs[i] * g4.x + e4.x);
        da[1] = tf32c((f01.y - mu[i]) * rs[i] * g4.y + e4.y);
        da[2] = tf32c((f23.x - mu[i]) * rs[i] * g4.z + e4.z);
        da[3] = tf32c((f23.y - mu[i]) * rs[i] * g4.w + e4.w);
        unsigned* db = &Bs[row * 36 + c4 * 4];
        db[0] = tf32c(bv[i].x); db[1] = tf32c(bv[i].y);
        db[2] = tf32c(bv[i].z); db[3] = tf32c(bv[i].w);
    }
    __syncthreads();
    for (int st = 0; st < 8; st++) {
        const unsigned* Ab = As + (st & 1) * 4608;
        const unsigned* Bb = Bs + (st & 1) * 4608;
        if (st < 7) {
            const int k0 = (st + 1) * 32;
#pragma unroll
            for (int i = 0; i < 4; i++) {
                ahx[i] = *(const uint2*)&g_xth[(m0 + r0 + 32 * i) * 256 + k0 + c4 * 4];
                bv[i]  = *(const float4*)&w[(n0 + r0 + 32 * i) * 256 + k0 + c4 * 4];
            }
            g4 = *(const float4*)&lg[k0 + c4 * 4];
            e4 = *(const float4*)&lb[k0 + c4 * 4];
        }
#pragma unroll
        for (int k8 = 0; k8 < 4; k8++) {
            const int kb = k8 * 8;
            unsigned af[4][4], bf[4][2];
#pragma unroll
            for (int mf = 0; mf < 4; mf++) {
                int m = wm * 64 + mf * 16 + g;
                af[mf][0] = Ab[m * 36 + kb + t4];
                af[mf][1] = Ab[(m + 8) * 36 + kb + t4];
                af[mf][2] = Ab[m * 36 + kb + t4 + 4];
                af[mf][3] = Ab[(m + 8) * 36 + kb + t4 + 4];
            }
#pragma unroll
            for (int nf = 0; nf < 4; nf++) {
                int n = wn * 32 + nf * 8 + g;
                bf[nf][0] = Bb[n * 36 + kb + t4];
                bf[nf][1] = Bb[n * 36 + kb + t4 + 4];
            }
#pragma unroll
            for (int mf = 0; mf < 4; mf++)
#pragma unroll
                for (int nf = 0; nf < 4; nf++)
                    mma8(acc[mf][nf], af[mf], bf[nf]);
        }
        if (st < 7) {
            unsigned* Aw = As + ((st + 1) & 1) * 4608;
            unsigned* Bw = Bs + ((st + 1) & 1) * 4608;
#pragma unroll
            for (int i = 0; i < 4; i++) {
                int row = r0 + 32 * i;
                float2 f01 = __half22float2(*(const __half2*)&ahx[i].x);
                float2 f23 = __half22float2(*(const __half2*)&ahx[i].y);
                unsigned* da = &Aw[row * 36 + c4 * 4];
                da[0] = tf32c((f01.x - mu[i]) * rs[i] * g4.x + e4.x);
                da[1] = tf32c((f01.y - mu[i]) * rs[i] * g4.y + e4.y);
                da[2] = tf32c((f23.x - mu[i]) * rs[i] * g4.z + e4.z);
                da[3] = tf32c((f23.y - mu[i]) * rs[i] * g4.w + e4.w);
                unsigned* db = &Bw[row * 36 + c4 * 4];
                db[0] = tf32c(bv[i].x); db[1] = tf32c(bv[i].y);
                db[2] = tf32c(bv[i].z); db[3] = tf32c(bv[i].w);
            }
            __syncthreads();
        }
    }
    __half* dsth = (n0 < 512) ? g_xmh : g_zh;
    const int nb = (n0 < 512) ? n0 : (n0 - 512);
#pragma unroll
    for (int mf = 0; mf < 4; mf++) {
        int m = m0 + wm * 64 + mf * 16 + g;
#pragma unroll
        for (int nf = 0; nf < 4; nf++) {
            int n = nb + wn * 32 + nf * 8 + 2 * t4;
            *(__half2*)&dsth[m * 512 + n]       = __floats2half2_rn(acc[mf][nf][0], acc[mf][nf][1]);
            *(__half2*)&dsth[(m + 8) * 512 + n] = __floats2half2_rn(acc[mf][nf][2], acc[mf][nf][3]);
        }
    }
}

// =====================================================================
// K5: causal depthwise conv (k=3) + SiLU -> uh fp16 ; {u, silu(z)} fp16
// =====================================================================
__global__ void k_conv4(const float* __restrict__ cw, const float* __restrict__ cb) {
    const int g = blockIdx.x * blockDim.x + threadIdx.x;
    const int base = g * 4;
    const int d = base & 511;
    const int l = (base >> 9) & 4095;
    uint2 h2 = *(const uint2*)&g_xmh[base];
    float2 x2a = __half22float2(*(const __half2*)&h2.x);
    float2 x2b = __half22float2(*(const __half2*)&h2.y);
    float2 x1a = make_float2(0.f, 0.f), x1b = make_float2(0.f, 0.f);
    float2 x0a = make_float2(0.f, 0.f), x0b = make_float2(0.f, 0.f);
    if (l >= 1) {
        uint2 t = *(const uint2*)&g_xmh[base - 512];
        x1a = __half22float2(*(const __half2*)&t.x);
        x1b = __half22float2(*(const __half2*)&t.y);
    }
    if (l >= 2) {
        uint2 t = *(const uint2*)&g_xmh[base - 1024];
        x0a = __half22float2(*(const __half2*)&t.x);
        x0b = __half22float2(*(const __half2*)&t.y);
    }
    float4 w0 = *(const float4*)&cw[d * 3];
    float4 w1 = *(const float4*)&cw[d * 3 + 4];
    float4 w2 = *(const float4*)&cw[d * 3 + 8];
    float4 cb4 = *(const float4*)&cb[d];
    float f[12] = {w0.x, w0.y, w0.z, w0.w, w1.x, w1.y, w1.z, w1.w, w2.x, w2.y, w2.z, w2.w};
    float a0 = x0a.x * f[0] + x1a.x * f[1]  + x2a.x * f[2]  + cb4.x;
    float a1 = x0a.y * f[3] + x1a.y * f[4]  + x2a.y * f[5]  + cb4.y;
    float a2 = x0b.x * f[6] + x1b.x * f[7]  + x2b.x * f[8]  + cb4.z;
    float a3 = x0b.y * f[9] + x1b.y * f[10] + x2b.y * f[11] + cb4.w;
    float u0 = a0 / (1.f + __expf(-a0));
    float u1 = a1 / (1.f + __expf(-a1));
    float u2 = a2 / (1.f + __expf(-a2));
    float u3 = a3 / (1.f + __expf(-a3));
    uint2 uh;
    *(__half2*)&uh.x = __floats2half2_rn(u0, u1);
    *(__half2*)&uh.y = __floats2half2_rn(u2, u3);
    *(uint2*)&g_uh[base] = uh;
    uint2 zh = *(const uint2*)&g_zh[base];
    float2 z01 = __half22float2(*(const __half2*)&zh.x);
    float2 z23 = __half22float2(*(const __half2*)&zh.y);
    uint4 uz;
    *(__half2*)&uz.x = __floats2half2_rn(u0, z01.x / (1.f + __expf(-z01.x)));
    *(__half2*)&uz.y = __floats2half2_rn(u1, z01.y / (1.f + __expf(-z01.y)));
    *(__half2*)&uz.z = __floats2half2_rn(u2, z23.x / (1.f + __expf(-z23.x)));
    *(__half2*)&uz.w = __floats2half2_rn(u3, z23.y / (1.f + __expf(-z23.y)));
    *(uint4*)&g_uz[base] = uz;
}

// =====================================================================
// K6: x_proj GEMM — TF32 TC 64x64 tiles (full-wave grid), fp16 A source
// =====================================================================
__global__ void __launch_bounds__(256)
k_xproj_tc(const float* __restrict__ w) {
    __shared__ __align__(16) unsigned As[64 * 36];
    __shared__ __align__(16) unsigned Bs[64 * 36];
    const int m0 = blockIdx.x * 64;
    const int tid = threadIdx.x, lane = tid & 31, wid = tid >> 5;
    const int wm = wid >> 1, wn = wid & 1;        // 4 x 2 warps
    const int g = lane >> 2, t4 = lane & 3;
    const int r0 = tid >> 2, q8 = (tid & 3) * 8;  // 64 rows x 8 cols
    float acc[4][4] = {};
    for (int st = 0; st < 16; st++) {
        const int k0 = st * 32;
        // A: u fp16 64x32
        uint2 a0 = *(const uint2*)&g_uh[(m0 + r0) * 512 + k0 + q8];
        uint2 a1 = *(const uint2*)&g_uh[(m0 + r0) * 512 + k0 + q8 + 4];
        float2 f0 = __half22float2(*(const __half2*)&a0.x);
        float2 f1 = __half22float2(*(const __half2*)&a0.y);
        float2 f2 = __half22float2(*(const __half2*)&a1.x);
        float2 f3 = __half22float2(*(const __half2*)&a1.y);
        unsigned* da = &As[r0 * 36 + q8];
        da[0] = tf32c(f0.x); da[1] = tf32c(f0.y); da[2] = tf32c(f1.x); da[3] = tf32c(f1.y);
        da[4] = tf32c(f2.x); da[5] = tf32c(f2.y); da[6] = tf32c(f3.x); da[7] = tf32c(f3.y);
        // B: x_proj_w [n][k] 64x32 (48 live rows)
        float4 b0 = make_float4(0.f, 0.f, 0.f, 0.f), b1 = b0;
        if (r0 < 48) {
            b0 = *(const float4*)&w[r0 * 512 + k0 + q8];
            b1 = *(const float4*)&w[r0 * 512 + k0 + q8 + 4];
        }
        unsigned* db = &Bs[r0 * 36 + q8];
        db[0] = tf32c(b0.x); db[1] = tf32c(b0.y); db[2] = tf32c(b0.z); db[3] = tf32c(b0.w);
        db[4] = tf32c(b1.x); db[5] = tf32c(b1.y); db[6] = tf32c(b1.z); db[7] = tf32c(b1.w);
        __syncthreads();
#pragma unroll
        for (int k8 = 0; k8 < 4; k8++) {
            const int kb = k8 * 8;
            unsigned af[4], bf[4][2];
            {
                int m = wm * 16 + g;
                af[0] = As[m * 36 + kb + t4];
                af[1] = As[(m + 8) * 36 + kb + t4];
                af[2] = As[m * 36 + kb + t4 + 4];
                af[3] = As[(m + 8) * 36 + kb + t4 + 4];
            }
#pragma unroll
            for (int nf = 0; nf < 4; nf++) {
                int n = wn * 32 + nf * 8 + g;
                bf[nf][0] = Bs[n * 36 + kb + t4];
                bf[nf][1] = Bs[n * 36 + kb + t4 + 4];
            }
#pragma unroll
            for (int nf = 0; nf < 4; nf++)
                mma8(acc[nf], af, bf[nf]);
        }
        __syncthreads();
    }
    float* bccf = (float*)g_bcc;
#pragma unroll
    for (int nf = 0; nf < 4; nf++) {
#pragma unroll
        for (int half = 0; half < 2; half++) {
            int gm = m0 + wm * 16 + g + half * 8;
#pragma unroll
            for (int jj = 0; jj < 2; jj++) {
                int gn = wn * 32 + nf * 8 + 2 * t4 + jj;
                float v = acc[nf][half * 2 + jj];
                if (gn < 16)      g_dtin[gm * 16 + gn] = v;
                else if (gn < 32) bccf[gm * 32 + 2 * (gn - 16)] = v;
                else if (gn < 48) bccf[gm * 32 + 2 * (gn - 32) + 1] = v;
            }
        }
    }
}

// =====================================================================
// K7: dt_proj GEMM (K=16) + softplus; writes {dt, dt*u} fp16
// =====================================================================
__global__ void k_dtproj(const float* __restrict__ w, const float* __restrict__ dtb) {
    __shared__ float As[16][65];
    __shared__ float Bs[16][65];
    const int m0 = blockIdx.x * 64;
    const int n0 = blockIdx.y * 64;
    const int tid = threadIdx.x;
    const int tx = tid & 15, ty = tid >> 4;
    float acc[4][4] = {};
#pragma unroll
    for (int i = 0; i < 4; i++) {
        int idx = tid + i * 256;
        int m = idx >> 4, kk = idx & 15;
        As[kk][m] = g_dtin[(m0 + m) * 16 + kk];
    }
#pragma unroll
    for (int i = 0; i < 4; i++) {
        int idx = tid + i * 256;
        int n = idx >> 4, kk = idx & 15;
        Bs[kk][n] = w[(n0 + n) * 16 + kk];
    }
    __syncthreads();
#pragma unroll
    for (int kk = 0; kk < 16; kk++) {
        float a[4], c[4];
#pragma unroll
        for (int i = 0; i < 4; i++) a[i] = As[kk][ty * 4 + i];
#pragma unroll
        for (int j = 0; j < 4; j++) c[j] = Bs[kk][tx * 4 + j];
#pragma unroll
        for (int i = 0; i < 4; i++)
#pragma unroll
            for (int j = 0; j < 4; j++) acc[i][j] += a[i] * c[j];
    }
#pragma unroll
    for (int i = 0; i < 4; i++) {
        int gm = m0 + ty * 4 + i;
        uint2 uh = *(const uint2*)&g_uh[gm * 512 + n0 + tx * 4];
        float2 u01 = __half22float2(*(const __half2*)&uh.x);
        float2 u23 = __half22float2(*(const __half2*)&uh.y);
        float um[4] = {u01.x, u01.y, u23.x, u23.y};
#pragma unroll
        for (int j = 0; j < 4; j++) {
            int gn = n0 + tx * 4 + j;
            float x = acc[i][j] + dtb[gn];
            float sp = (x > 20.f) ? x : log1pf(__expf(x));
            g_a[gm * 512 + gn] = __floats2half2_rn(sp, sp * um[j]);
        }
    }
}

// =====================================================================
// K8: scan pass 1 — warp = 4 channels x 8 lanes x 2 states/lane
// =====================================================================
__global__ void __launch_bounds__(256)
k_scan1(const float* __restrict__ alog) {
    const int w    = (blockIdx.x * blockDim.x + threadIdx.x) >> 5;
    const int lane = threadIdx.x & 31;
    const int chunk = w & (NCH - 1);
    const int dq   = (w >> 5) & 127;
    const int b    = w >> 12;
    const int c2 = lane >> 3, s8 = lane & 7;
    const int d  = dq * 4 + c2;
    const int s0 = 2 * s8;
    const float An2a = -__expf(alog[d * 16 + s0])     * LOG2E;
    const float An2b = -__expf(alog[d * 16 + s0 + 1]) * LOG2E;
    float2 h = make_float2(0.f, 0.f);
    float2 P = make_float2(1.f, 1.f);
    const int l0 = chunk * CT_;
    const __half2* ap = g_a + (size_t)(b * LL + l0) * 512 + d;
    const float4*  bp = (const float4*)(g_bcc + (size_t)(b * LL + l0) * 16) + s8;
#pragma unroll 8
    for (int t = 0; t < CT_; t++) {
        float2 av = __half22float2(ap[t * 512]);
        float4 bc = bp[t * 8];
        float dAa = exp2f(av.x * An2a);
        float dAb = exp2f(av.x * An2b);
        h.x = fmaf(dAa, h.x, av.y * bc.x);
        h.y = fmaf(dAb, h.y, av.y * bc.z);
        P.x *= dAa; P.y *= dAb;
    }
    const int tI = (b * 512 + d) * 16 + s0;
    *(float2*)&g_P[chunk * TT_ + tI]  = P;
    *(float2*)&g_Hc[chunk * TT_ + tI] = h;
}

// =====================================================================
// K9: chunk combine — materialize prefix states (coalesced float2)
// =====================================================================
__global__ void k_comb() {
    const int tI = (blockIdx.x * blockDim.x + threadIdx.x) * 2;  // TT_/2 threads
    float2 h = make_float2(0.f, 0.f);
    for (int c = 0; c < NCH; c++) {
        *(float2*)&g_hini[c * TT_ + tI] = h;
        float2 Pv = *(const float2*)&g_P[c * TT_ + tI];
        float2 Hv = *(const float2*)&g_Hc[c * TT_ + tI];
        h.x = Pv.x * h.x + Hv.x;
        h.y = Pv.y * h.y + Hv.y;
    }
}

// =====================================================================
// K10: scan pass 2 — load prefix, replay, y (fp16 out)
// =====================================================================
__global__ void __launch_bounds__(256)
k_scan2(const float* __restrict__ alog, const float* __restrict__ Dp) {
    const int w    = (blockIdx.x * blockDim.x + threadIdx.x) >> 5;
    const int lane = threadIdx.x & 31;
    const int chunk = w & (NCH - 1);
    const int dq   = (w >> 5) & 127;
    const int b    = w >> 12;
    const int c2 = lane >> 3, s8 = lane & 7;
    const int d  = dq * 4 + c2;
    const int s0 = 2 * s8;
    const float An2a = -__expf(alog[d * 16 + s0])     * LOG2E;
    const float An2b = -__expf(alog[d * 16 + s0 + 1]) * LOG2E;
    const float Dv = Dp[d];
    const int tI = (b * 512 + d) * 16 + s0;
    float2 h = *(const float2*)&g_hini[chunk * TT_ + tI];
    const int l0 = chunk * CT_;
    const __half2* ap = g_a  + (size_t)(b * LL + l0) * 512 + d;
    const float4*  bp = (const float4*)(g_bcc + (size_t)(b * LL + l0) * 16) + s8;
    const __half2* up = g_uz + (size_t)(b * LL + l0) * 512 + d;
    __half* yp = g_yfin + (size_t)(b * LL + l0) * 512 + d;
#pragma unroll 4
    for (int t = 0; t < CT_; t++) {
        float2 av = __half22float2(ap[t * 512]);
        float4 bc = bp[t * 8];
        float dAa = exp2f(av.x * An2a);
        float dAb = exp2f(av.x * An2b);
        h.x = fmaf(dAa, h.x, av.y * bc.x);
        h.y = fmaf(dAb, h.y, av.y * bc.z);
        float part = h.x * bc.y + h.y * bc.w;
        part += __shfl_xor_sync(0xffffffffu, part, 1);
        part += __shfl_xor_sync(0xffffffffu, part, 2);
        part += __shfl_xor_sync(0xffffffffu, part, 4);
        if (s8 == 0) {
            float2 uzv = __half22float2(up[t * 512]);
            yp[t * 512] = __float2half((part + uzv.x * Dv) * uzv.y);
        }
    }
}

// =====================================================================
// K11: out_proj GEMM — TF32 TC, fp16 A source, double-buffered,
//      residual + NCHW scatter
// =====================================================================
__global__ void __launch_bounds__(256)
k_outproj_tc(const float* __restrict__ w, float* __restrict__ out) {
    extern __shared__ unsigned dyn[];
    unsigned* As = dyn;
    unsigned* Bs = dyn + 2 * 4608;
    const int m0 = blockIdx.x * 128, n0 = blockIdx.y * 128;
    const int tid = threadIdx.x, lane = tid & 31, wid = tid >> 5;
    const int wm = wid >> 2, wn = wid & 3;
    const int g = lane >> 2, t4 = lane & 3;
    const int r0 = tid >> 3, c4 = tid & 7;
    float acc[4][4][4] = {};
    uint2 ah[4]; float4 bv[4];
#pragma unroll
    for (int i = 0; i < 4; i++) {
        ah[i] = *(const uint2*)&g_yfin[(m0 + r0 + 32 * i) * 512 + c4 * 4];
        bv[i] = *(const float4*)&w[(n0 + r0 + 32 * i) * 512 + c4 * 4];
    }
#pragma unroll
    for (int i = 0; i < 4; i++) {
        int row = r0 + 32 * i;
        float2 f01 = __half22float2(*(const __half2*)&ah[i].x);
        float2 f23 = __half22float2(*(const __half2*)&ah[i].y);
        unsigned* da = &As[row * 36 + c4 * 4];
        da[0] = tf32c(f01.x); da[1] = tf32c(f01.y);
        da[2] = tf32c(f23.x); da[3] = tf32c(f23.y);
        unsigned* db = &Bs[row * 36 + c4 * 4];
        db[0] = tf32c(bv[i].x); db[1] = tf32c(bv[i].y);
        db[2] = tf32c(bv[i].z); db[3] = tf32c(bv[i].w);
    }
    __syncthreads();
    for (int st = 0; st < 16; st++) {
        const unsigned* Ab = As + (st & 1) * 4608;
        const unsigned* Bb = Bs + (st & 1) * 4608;
        if (st < 15) {
            const int k0 = (st + 1) * 32;
#pragma unroll
            for (int i = 0; i < 4; i++) {
                ah[i] = *(const uint2*)&g_yfin[(m0 + r0 + 32 * i) * 512 + k0 + c4 * 4];
                bv[i] = *(const float4*)&w[(n0 + r0 + 32 * i) * 512 + k0 + c4 * 4];
            }
        }
#pragma unroll
        for (int k8 = 0; k8 < 4; k8++) {
            const int kb = k8 * 8;
            unsigned af[4][4], bf[4][2];
#pragma unroll
            for (int mf = 0; mf < 4; mf++) {
                int m = wm * 64 + mf * 16 + g;
                af[mf][0] = Ab[m * 36 + kb + t4];
                af[mf][1] = Ab[(m + 8) * 36 + kb + t4];
                af[mf][2] = Ab[m * 36 + kb + t4 + 4];
                af[mf][3] = Ab[(m + 8) * 36 + kb + t4 + 4];
            }
#pragma unroll
            for (int nf = 0; nf < 4; nf++) {
                int n = wn * 32 + nf * 8 + g;
                bf[nf][0] = Bb[n * 36 + kb + t4];
                bf[nf][1] = Bb[n * 36 + kb + t4 + 4];
            }
#pragma unroll
            for (int mf = 0; mf < 4; mf++)
#pragma unroll
                for (int nf = 0; nf < 4; nf++)
                    mma8(acc[mf][nf], af[mf], bf[nf]);
        }
        if (st < 15) {
            unsigned* Aw = As + ((st + 1) & 1) * 4608;
            unsigned* Bw = Bs + ((st + 1) & 1) * 4608;
#pragma unroll
            for (int i = 0; i < 4; i++) {
                int row = r0 + 32 * i;
                float2 f01 = __half22float2(*(const __half2*)&ah[i].x);
                float2 f23 = __half22float2(*(const __half2*)&ah[i].y);
                unsigned* da = &Aw[row * 36 + c4 * 4];
                da[0] = tf32c(f01.x); da[1] = tf32c(f01.y);
                da[2] = tf32c(f23.x); da[3] = tf32c(f23.y);
                unsigned* db = &Bw[row * 36 + c4 * 4];
                db[0] = tf32c(bv[i].x); db[1] = tf32c(bv[i].y);
                db[2] = tf32c(bv[i].z); db[3] = tf32c(bv[i].w);
            }
            __syncthreads();
        }
    }
    const int bb = m0 >> 12;
#pragma unroll
    for (int mf = 0; mf < 4; mf++) {
        int m = m0 + wm * 64 + mf * 16 + g;
        int l = m & 4095;
#pragma unroll
        for (int nf = 0; nf < 4; nf++) {
            int n = n0 + wn * 32 + nf * 8 + 2 * t4;
            size_t i0 = (size_t)(bb * 256 + n) * 4096 + l;
            size_t i1 = i0 + 4096;
            out[i0]     = acc[mf][nf][0] + g_fused[i0];
            out[i1]     = acc[mf][nf][1] + g_fused[i1];
            out[i0 + 8] = acc[mf][nf][2] + g_fused[i0 + 8];
            out[i1 + 8] = acc[mf][nf][3] + g_fused[i1 + 8];
        }
    }
}

// =====================================================================
extern "C" void kernel_launch(void* const* d_in, const int* in_sizes, int n_in,
                              void* d_out, int out_size) {
    const float* resnet = (const float*)d_in[0];
    const float* scp    = (const float*)d_in[1];
    const float* scpw   = (const float*)d_in[2];
    const float* sg = (const float*)d_in[3];
    const float* sb = (const float*)d_in[4];
    const float* sm = (const float*)d_in[5];
    const float* sv = (const float*)d_in[6];
    const float* rg = (const float*)d_in[7];
    const float* rb = (const float*)d_in[8];
    const float* rm = (const float*)d_in[9];
    const float* rv = (const float*)d_in[10];
    const float* lg = (const float*)d_in[11];
    const float* lb = (const float*)d_in[12];
    const float* inw = (const float*)d_in[13];
    const float* cw  = (const float*)d_in[14];
    const float* cb  = (const float*)d_in[15];
    const float* xw  = (const float*)d_in[16];
    const float* dtw = (const float*)d_in[17];
    const float* dtb = (const float*)d_in[18];
    const float* alog = (const float*)d_in[19];
    const float* Dp   = (const float*)d_in[20];
    const float* ow   = (const float*)d_in[21];
    float* out = (float*)d_out;

    const int DYN = 4 * 4608 * 4;  // 73728 bytes (double-buffered As+Bs)
    cudaFuncSetAttribute(k_inproj_tc, cudaFuncAttributeMaxDynamicSharedMemorySize, DYN);
    cudaFuncSetAttribute(k_outproj_tc, cudaFuncAttributeMaxDynamicSharedMemorySize, DYN);

    k_scp_tc   <<<dim3(4, 16, 2), 256>>>(scp, scpw, sg, sb, sm, sv);
    k_fuse     <<<dim3(128, 8, 2), dim3(32, 8)>>>(resnet, rg, rb, rm, rv);
    k_inproj_tc<<<dim3(64, 8), 256, DYN>>>(inw, lg, lb);
    k_conv4    <<<(NB * LL * DI_) / 1024, 256>>>(cw, cb);
    k_xproj_tc <<<128, 256>>>(xw);
    k_dtproj   <<<dim3(128, 8), 256>>>(dtw, dtb);
    k_scan1    <<<1024, 256>>>(alog);
    k_comb     <<<32, 256>>>();
    k_scan2    <<<1024, 256>>>(alog, Dp);
    k_outproj_tc<<<dim3(64, 2), 256, DYN>>>(ow, out);
}

// round 15
// speedup vs baseline: 1.4457x; 1.4457x over previous
#include <cuda_runtime.h>
#include <cuda_fp16.h>

// ---------------- problem constants ----------------
#define NB   2
#define CR_  256
#define CS_  512
#define LL   4096     // 64*64
#define PS_  1024     // 32*32
#define DI_  512
#define DS_  16
#define NCH  32       // scan chunks
#define CT_  128      // chunk length (NCH*CT_ == LL)
#define TT_  (NB*DI_*DS_)   // 16384 scan tracks
#define EPSF 1e-5f
#define LOG2E 1.4426950408889634f

__device__ __forceinline__ unsigned tf32c(float x) {
    unsigned r; asm("cvt.rna.tf32.f32 %0, %1;" : "=r"(r) : "f"(x)); return r;
}
__device__ __forceinline__ void mma8(float* c, const unsigned* a, const unsigned* b) {
    asm volatile("mma.sync.aligned.m16n8k8.row.col.f32.tf32.tf32.f32 "
        "{%0,%1,%2,%3}, {%4,%5,%6,%7}, {%8,%9}, {%0,%1,%2,%3};"
        : "+f"(c[0]), "+f"(c[1]), "+f"(c[2]), "+f"(c[3])
        : "r"(a[0]), "r"(a[1]), "r"(a[2]), "r"(a[3]), "r"(b[0]), "r"(b[1]));
}

// ---------------- scratch (static device allocs only) ----------------
__device__ float   g_sp   [NB*CR_*PS_];
__device__ float   g_fused[NB*CR_*LL];
__device__ __half  g_xth  [NB*LL*CR_];    // fused transposed, fp16
__device__ float2  g_psum [NB*LL*8];
__device__ __half  g_xmh  [NB*LL*DI_];    // xm fp16
__device__ __half  g_zh   [NB*LL*DI_];    // z fp16
__device__ __half  g_uh   [NB*LL*DI_];    // u fp16
__device__ float   g_dtin [NB*LL*DS_];
__device__ float2  g_bcc  [NB*LL*DS_];    // {B_s, C_s} fp32 interleaved
__device__ __half2 g_a    [NB*LL*DI_];    // {dt, dt*u} fp16
__device__ __half2 g_uz   [NB*LL*DI_];    // {u, silu(z)} fp16
__device__ float   g_P    [NCH*TT_];      // chunk-major, state-pairs contiguous
__device__ float   g_Hc   [NCH*TT_];
__device__ float   g_hini [NCH*TT_];      // materialized chunk-prefix states
__device__ __half  g_yfin [NB*LL*DI_];    // y fp16

// =====================================================================
// K1: scp 1x1 conv GEMM + BN — TF32 TC, B transpose-staged (stride 33)
// =====================================================================
__global__ void __launch_bounds__(256)
k_scp_tc(const float* __restrict__ scp, const float* __restrict__ w,
         const float* __restrict__ gg, const float* __restrict__ bb,
         const float* __restrict__ mm, const float* __restrict__ vv) {
    __shared__ __align__(16) unsigned As[128 * 36];   // W  [o][k]
    __shared__ __align__(16) unsigned Bs[128 * 33];   // scp^T [p][k]
    const int b  = blockIdx.z;
    const int m0 = blockIdx.x * 128;   // o
    const int n0 = blockIdx.y * 128;   // p
    const int tid = threadIdx.x, lane = tid & 31, wid = tid >> 5;
    const int wm = wid >> 2, wn = wid & 3;
    const int g = lane >> 2, t4 = lane & 3;
    const int r0 = tid >> 3, c4 = tid & 7;
    const int kq = tid >> 6, pq2 = (tid & 63) * 2;
    float acc[4][4][4] = {};
    float4 av[4]; float2 bvv[8];
#pragma unroll
    for (int i = 0; i < 4; i++)
        av[i] = *(const float4*)&w[(m0 + r0 + 32 * i) * 512 + c4 * 4];
#pragma unroll
    for (int j = 0; j < 8; j++)
        bvv[j] = *(const float2*)&scp[(b * 512 + j * 4 + kq) * 1024 + n0 + pq2];
    for (int st = 0; st < 16; st++) {
#pragma unroll
        for (int i = 0; i < 4; i++) {
            unsigned* da = &As[(r0 + 32 * i) * 36 + c4 * 4];
            da[0] = tf32c(av[i].x); da[1] = tf32c(av[i].y);
            da[2] = tf32c(av[i].z); da[3] = tf32c(av[i].w);
        }
#pragma unroll
        for (int j = 0; j < 8; j++) {
            Bs[pq2 * 33 + j * 4 + kq]       = tf32c(bvv[j].x);
            Bs[(pq2 + 1) * 33 + j * 4 + kq] = tf32c(bvv[j].y);
        }
        __syncthreads();
        if (st < 15) {
            const int k0 = (st + 1) * 32;
#pragma unroll
            for (int i = 0; i < 4; i++)
                av[i] = *(const float4*)&w[(m0 + r0 + 32 * i) * 512 + k0 + c4 * 4];
#pragma unroll
            for (int j = 0; j < 8; j++)
                bvv[j] = *(const float2*)&scp[(b * 512 + k0 + j * 4 + kq) * 1024 + n0 + pq2];
        }
#pragma unroll
        for (int k8 = 0; k8 < 4; k8++) {
            const int kb = k8 * 8;
            unsigned af[4][4], bf[4][2];
#pragma unroll
            for (int mf = 0; mf < 4; mf++) {
                int m = wm * 64 + mf * 16 + g;
                af[mf][0] = As[m * 36 + kb + t4];
                af[mf][1] = As[(m + 8) * 36 + kb + t4];
                af[mf][2] = As[m * 36 + kb + t4 + 4];
                af[mf][3] = As[(m + 8) * 36 + kb + t4 + 4];
            }
#pragma unroll
            for (int nf = 0; nf < 4; nf++) {
                int n = wn * 32 + nf * 8 + g;
                bf[nf][0] = Bs[n * 33 + kb + t4];
                bf[nf][1] = Bs[n * 33 + kb + t4 + 4];
            }
#pragma unroll
            for (int mf = 0; mf < 4; mf++)
#pragma unroll
                for (int nf = 0; nf < 4; nf++)
                    mma8(acc[mf][nf], af[mf], bf[nf]);
        }
        __syncthreads();
    }
#pragma unroll
    for (int mf = 0; mf < 4; mf++) {
        int o = m0 + wm * 64 + mf * 16 + g;
        float iv0 = gg[o] * rsqrtf(vv[o] + EPSF);
        float be0 = bb[o] - mm[o] * iv0;
        float iv1 = gg[o + 8] * rsqrtf(vv[o + 8] + EPSF);
        float be1 = bb[o + 8] - mm[o + 8] * iv1;
#pragma unroll
        for (int nf = 0; nf < 4; nf++) {
            int p = n0 + wn * 32 + nf * 8 + 2 * t4;
            float* dp  = &g_sp[(b * 256 + o) * 1024 + p];
            float* dp8 = &g_sp[(b * 256 + o + 8) * 1024 + p];
            dp[0]  = acc[mf][nf][0] * iv0 + be0;
            dp[1]  = acc[mf][nf][1] * iv0 + be0;
            dp8[0] = acc[mf][nf][2] * iv1 + be1;
            dp8[1] = acc[mf][nf][3] * iv1 + be1;
        }
    }
}

// =====================================================================
// K2: fused = BN(resnet) + bilinear(sp); (B,C,HW) fp32 + (B,HW,C) fp16
//     + LN psums
// =====================================================================
__global__ void k_fuse(const float* __restrict__ res,
                       const float* __restrict__ rg, const float* __restrict__ rb,
                       const float* __restrict__ rm, const float* __restrict__ rv) {
    __shared__ float tile[32][33];
    const int b  = blockIdx.z;
    const int c0 = blockIdx.y * 32;
    const int l0 = blockIdx.x * 32;
    const int tx = threadIdx.x, ty = threadIdx.y;
    const int l = l0 + tx;
    const int h = l >> 6, wq = l & 63;
    float sh = h * 0.5f - 0.25f;
    float sw = wq * 0.5f - 0.25f;
    int h0 = (int)floorf(sh); float fh = sh - (float)h0;
    int w0 = (int)floorf(sw); float fw = sw - (float)w0;
    int h0c = max(h0, 0), h1c = min(h0 + 1, 31);
    int w0c = max(w0, 0), w1c = min(w0 + 1, 31);
#pragma unroll
    for (int i = 0; i < 4; i++) {
        int c = c0 + ty + i * 8;
        float inv  = rg[c] * rsqrtf(rv[c] + EPSF);
        float beta = rb[c] - rm[c] * inv;
        float val = res[(b * 256 + c) * 4096 + l] * inv + beta;
        const float* spb = g_sp + (b * 256 + c) * 1024;
        float s00 = spb[h0c * 32 + w0c], s01 = spb[h0c * 32 + w1c];
        float s10 = spb[h1c * 32 + w0c], s11 = spb[h1c * 32 + w1c];
        val += (1.f - fh) * ((1.f - fw) * s00 + fw * s01)
             +        fh  * ((1.f - fw) * s10 + fw * s11);
        g_fused[(b * 256 + c) * 4096 + l] = val;
        tile[ty + i * 8][tx] = val;
    }
    __syncthreads();
#pragma unroll
    for (int i = 0; i < 4; i++) {
        int c  = c0 + tx;
        int ll = l0 + ty + i * 8;
        g_xth[(b * 4096 + ll) * 256 + c] = __float2half(tile[tx][ty + i * 8]);
    }
    const int tid = ty * 32 + tx;
    if (tid < 32) {
        float s = 0.f, q = 0.f;
#pragma unroll
        for (int cc = 0; cc < 32; cc++) {
            float v = tile[cc][tid];
            s += v; q += v * v;
        }
        g_psum[(b * 4096 + l0 + tid) * 8 + (c0 >> 5)] = make_float2(s, q);
    }
}

// =====================================================================
// K4: in_proj GEMM — TF32 TC, fp16 A source, double-buffered, fused LN
// =====================================================================
__global__ void __launch_bounds__(256)
k_inproj_tc(const float* __restrict__ w,
            const float* __restrict__ lg, const float* __restrict__ lb) {
    extern __shared__ unsigned dyn[];
    unsigned* As = dyn;             // [2][128*36]
    unsigned* Bs = dyn + 2 * 4608;  // [2][128*36]
    __shared__ float s_mu[128], s_rs[128];
    const int m0 = blockIdx.x * 128, n0 = blockIdx.y * 128;
    const int tid = threadIdx.x, lane = tid & 31, wid = tid >> 5;
    const int wm = wid >> 2, wn = wid & 3;
    const int g = lane >> 2, t4 = lane & 3;
    if (tid < 128) {
        float s = 0.f, qq = 0.f;
#pragma unroll
        for (int i = 0; i < 8; i++) {
            float2 p = g_psum[(m0 + tid) * 8 + i];
            s += p.x; qq += p.y;
        }
        float mu = s * (1.f / 256.f);
        s_mu[tid] = mu;
        s_rs[tid] = rsqrtf(qq * (1.f / 256.f) - mu * mu + EPSF);
    }
    __syncthreads();
    const int r0 = tid >> 3, c4 = tid & 7;
    float mu[4], rs[4];
#pragma unroll
    for (int i = 0; i < 4; i++) { mu[i] = s_mu[r0 + 32 * i]; rs[i] = s_rs[r0 + 32 * i]; }
    float acc[4][4][4] = {};
    uint2 ahx[4]; float4 bv[4], g4, e4;
#pragma unroll
    for (int i = 0; i < 4; i++) {
        ahx[i] = *(const uint2*)&g_xth[(m0 + r0 + 32 * i) * 256 + c4 * 4];
        bv[i]  = *(const float4*)&w[(n0 + r0 + 32 * i) * 256 + c4 * 4];
    }
    g4 = *(const float4*)&lg[c4 * 4];
    e4 = *(const float4*)&lb[c4 * 4];
#pragma unroll
    for (int i = 0; i < 4; i++) {
        int row = r0 + 32 * i;
        float2 f01 = __half22float2(*(const __half2*)&ahx[i].x);
        float2 f23 = __half22float2(*(const __half2*)&ahx[i].y);
        unsigned* da = &As[row * 36 + c4 * 4];
        da[0] = tf32c((f01.x - mu[i]) * rs[i] * g4.x + e4.x);
        da[1] = tf32c((f01.y - mu[i]) * rs[i] * g4.y + e4.y);
        da[2] = tf32c((f23.x - mu[i]) * rs[i] * g4.z + e4.z);
        da[3] = tf32c((f23.y - mu[i]) * rs[i] * g4.w + e4.w);
        unsigned* db = &Bs[row * 36 + c4 * 4];
        db[0] = tf32c(bv[i].x); db[1] = tf32c(bv[i].y);
        db[2] = tf32c(bv[i].z); db[3] = tf32c(bv[i].w);
    }
    __syncthreads();
    for (int st = 0; st < 8; st++) {
        const unsigned* Ab = As + (st & 1) * 4608;
        const unsigned* Bb = Bs + (st & 1) * 4608;
        if (st < 7) {
            const int k0 = (st + 1) * 32;
#pragma unroll
            for (int i = 0; i < 4; i++) {
                ahx[i] = *(const uint2*)&g_xth[(m0 + r0 + 32 * i) * 256 + k0 + c4 * 4];
                bv[i]  = *(const float4*)&w[(n0 + r0 + 32 * i) * 256 + k0 + c4 * 4];
            }
            g4 = *(const float4*)&lg[k0 + c4 * 4];
            e4 = *(const float4*)&lb[k0 + c4 * 4];
        }
#pragma unroll
        for (int k8 = 0; k8 < 4; k8++) {
            const int kb = k8 * 8;
            unsigned af[4][4], bf[4][2];
#pragma unroll
            for (int mf = 0; mf < 4; mf++) {
                int m = wm * 64 + mf * 16 + g;
                af[mf][0] = Ab[m * 36 + kb + t4];
                af[mf][1] = Ab[(m + 8) * 36 + kb + t4];
                af[mf][2] = Ab[m * 36 + kb + t4 + 4];
                af[mf][3] = Ab[(m + 8) * 36 + kb + t4 + 4];
            }
#pragma unroll
            for (int nf = 0; nf < 4; nf++) {
                int n = wn * 32 + nf * 8 + g;
                bf[nf][0] = Bb[n * 36 + kb + t4];
                bf[nf][1] = Bb[n * 36 + kb + t4 + 4];
            }
#pragma unroll
            for (int mf = 0; mf < 4; mf++)
#pragma unroll
                for (int nf = 0; nf < 4; nf++)
                    mma8(acc[mf][nf], af[mf], bf[nf]);
        }
        if (st < 7) {
            unsigned* Aw = As + ((st + 1) & 1) * 4608;
            unsigned* Bw = Bs + ((st + 1) & 1) * 4608;
#pragma unroll
            for (int i = 0; i < 4; i++) {
                int row = r0 + 32 * i;
                float2 f01 = __half22float2(*(const __half2*)&ahx[i].x);
                float2 f23 = __half22float2(*(const __half2*)&ahx[i].y);
                unsigned* da = &Aw[row * 36 + c4 * 4];
                da[0] = tf32c((f01.x - mu[i]) * rs[i] * g4.x + e4.x);
                da[1] = tf32c((f01.y - mu[i]) * rs[i] * g4.y + e4.y);
                da[2] = tf32c((f23.x - mu[i]) * rs[i] * g4.z + e4.z);
                da[3] = tf32c((f23.y - mu[i]) * rs[i] * g4.w + e4.w);
                unsigned* db = &Bw[row * 36 + c4 * 4];
                db[0] = tf32c(bv[i].x); db[1] = tf32c(bv[i].y);
                db[2] = tf32c(bv[i].z); db[3] = tf32c(bv[i].w);
            }
            __syncthreads();
        }
    }
    __half* dsth = (n0 < 512) ? g_xmh : g_zh;
    const int nb = (n0 < 512) ? n0 : (n0 - 512);
#pragma unroll
    for (int mf = 0; mf < 4; mf++) {
        int m = m0 + wm * 64 + mf * 16 + g;
#pragma unroll
        for (int nf = 0; nf < 4; nf++) {
            int n = nb + wn * 32 + nf * 8 + 2 * t4;
            *(__half2*)&dsth[m * 512 + n]       = __floats2half2_rn(acc[mf][nf][0], acc[mf][nf][1]);
            *(__half2*)&dsth[(m + 8) * 512 + n] = __floats2half2_rn(acc[mf][nf][2], acc[mf][nf][3]);
        }
    }
}

// =====================================================================
// K5: causal depthwise conv (k=3) + SiLU -> uh fp16 ; {u, silu(z)} fp16
// =====================================================================
__global__ void k_conv4(const float* __restrict__ cw, const float* __restrict__ cb) {
    const int g = blockIdx.x * blockDim.x + threadIdx.x;
    const int base = g * 4;
    const int d = base & 511;
    const int l = (base >> 9) & 4095;
    uint2 h2 = *(const uint2*)&g_xmh[base];
    float2 x2a = __half22float2(*(const __half2*)&h2.x);
    float2 x2b = __half22float2(*(const __half2*)&h2.y);
    float2 x1a = make_float2(0.f, 0.f), x1b = make_float2(0.f, 0.f);
    float2 x0a = make_float2(0.f, 0.f), x0b = make_float2(0.f, 0.f);
    if (l >= 1) {
        uint2 t = *(const uint2*)&g_xmh[base - 512];
        x1a = __half22float2(*(const __half2*)&t.x);
        x1b = __half22float2(*(const __half2*)&t.y);
    }
    if (l >= 2) {
        uint2 t = *(const uint2*)&g_xmh[base - 1024];
        x0a = __half22float2(*(const __half2*)&t.x);
        x0b = __half22float2(*(const __half2*)&t.y);
    }
    float4 w0 = *(const float4*)&cw[d * 3];
    float4 w1 = *(const float4*)&cw[d * 3 + 4];
    float4 w2 = *(const float4*)&cw[d * 3 + 8];
    float4 cb4 = *(const float4*)&cb[d];
    float f[12] = {w0.x, w0.y, w0.z, w0.w, w1.x, w1.y, w1.z, w1.w, w2.x, w2.y, w2.z, w2.w};
    float a0 = x0a.x * f[0] + x1a.x * f[1]  + x2a.x * f[2]  + cb4.x;
    float a1 = x0a.y * f[3] + x1a.y * f[4]  + x2a.y * f[5]  + cb4.y;
    float a2 = x0b.x * f[6] + x1b.x * f[7]  + x2b.x * f[8]  + cb4.z;
    float a3 = x0b.y * f[9] + x1b.y * f[10] + x2b.y * f[11] + cb4.w;
    float u0 = a0 / (1.f + __expf(-a0));
    float u1 = a1 / (1.f + __expf(-a1));
    float u2 = a2 / (1.f + __expf(-a2));
    float u3 = a3 / (1.f + __expf(-a3));
    uint2 uh;
    *(__half2*)&uh.x = __floats2half2_rn(u0, u1);
    *(__half2*)&uh.y = __floats2half2_rn(u2, u3);
    *(uint2*)&g_uh[base] = uh;
    uint2 zh = *(const uint2*)&g_zh[base];
    float2 z01 = __half22float2(*(const __half2*)&zh.x);
    float2 z23 = __half22float2(*(const __half2*)&zh.y);
    uint4 uz;
    *(__half2*)&uz.x = __floats2half2_rn(u0, z01.x / (1.f + __expf(-z01.x)));
    *(__half2*)&uz.y = __floats2half2_rn(u1, z01.y / (1.f + __expf(-z01.y)));
    *(__half2*)&uz.z = __floats2half2_rn(u2, z23.x / (1.f + __expf(-z23.x)));
    *(__half2*)&uz.w = __floats2half2_rn(u3, z23.y / (1.f + __expf(-z23.y)));
    *(uint4*)&g_uz[base] = uz;
}

// =====================================================================
// K6: x_proj GEMM — TF32 TC 128x64 (48 live cols), fp16 A source
// =====================================================================
__global__ void __launch_bounds__(256)
k_xproj_tc(const float* __restrict__ w) {
    __shared__ __align__(16) unsigned As[128 * 36];
    __shared__ __align__(16) unsigned Bs[64 * 36];
    const int m0 = blockIdx.x * 128;
    const int tid = threadIdx.x, lane = tid & 31, wid = tid >> 5;
    const int wm = wid >> 1, wn = wid & 1;
    const int g = lane >> 2, t4 = lane & 3;
    const int r0 = tid >> 3, c4 = tid & 7;
    float acc[2][4][4] = {};
    uint2 ah[4]; float4 bv[2];
#pragma unroll
    for (int i = 0; i < 4; i++)
        ah[i] = *(const uint2*)&g_uh[(m0 + r0 + 32 * i) * 512 + c4 * 4];
#pragma unroll
    for (int i = 0; i < 2; i++) {
        int n = r0 + 32 * i;
        bv[i] = (n < 48) ? *(const float4*)&w[n * 512 + c4 * 4]
                         : make_float4(0.f, 0.f, 0.f, 0.f);
    }
    for (int st = 0; st < 16; st++) {
#pragma unroll
        for (int i = 0; i < 4; i++) {
            float2 f01 = __half22float2(*(const __half2*)&ah[i].x);
            float2 f23 = __half22float2(*(const __half2*)&ah[i].y);
            unsigned* da = &As[(r0 + 32 * i) * 36 + c4 * 4];
            da[0] = tf32c(f01.x); da[1] = tf32c(f01.y);
            da[2] = tf32c(f23.x); da[3] = tf32c(f23.y);
        }
#pragma unroll
        for (int i = 0; i < 2; i++) {
            unsigned* db = &Bs[(r0 + 32 * i) * 36 + c4 * 4];
            db[0] = tf32c(bv[i].x); db[1] = tf32c(bv[i].y);
            db[2] = tf32c(bv[i].z); db[3] = tf32c(bv[i].w);
        }
        __syncthreads();
        if (st < 15) {
            const int k0 = (st + 1) * 32;
#pragma unroll
            for (int i = 0; i < 4; i++)
                ah[i] = *(const uint2*)&g_uh[(m0 + r0 + 32 * i) * 512 + k0 + c4 * 4];
#pragma unroll
            for (int i = 0; i < 2; i++) {
                int n = r0 + 32 * i;
                bv[i] = (n < 48) ? *(const float4*)&w[n * 512 + k0 + c4 * 4]
                                 : make_float4(0.f, 0.f, 0.f, 0.f);
            }
        }
#pragma unroll
        for (int k8 = 0; k8 < 4; k8++) {
            const int kb = k8 * 8;
            unsigned af[2][4], bf[4][2];
#pragma unroll
            for (int mf = 0; mf < 2; mf++) {
                int m = wm * 32 + mf * 16 + g;
                af[mf][0] = As[m * 36 + kb + t4];
                af[mf][1] = As[(m + 8) * 36 + kb + t4];
                af[mf][2] = As[m * 36 + kb + t4 + 4];
                af[mf][3] = As[(m + 8) * 36 + kb + t4 + 4];
            }
#pragma unroll
            for (int nf = 0; nf < 4; nf++) {
                int n = wn * 32 + nf * 8 + g;
                bf[nf][0] = Bs[n * 36 + kb + t4];
                bf[nf][1] = Bs[n * 36 + kb + t4 + 4];
            }
#pragma unroll
            for (int mf = 0; mf < 2; mf++)
#pragma unroll
                for (int nf = 0; nf < 4; nf++)
                    mma8(acc[mf][nf], af[mf], bf[nf]);
        }
        __syncthreads();
    }
    float* bccf = (float*)g_bcc;
#pragma unroll
    for (int mf = 0; mf < 2; mf++) {
#pragma unroll
        for (int nf = 0; nf < 4; nf++) {
#pragma unroll
            for (int half = 0; half < 2; half++) {
                int gm = m0 + wm * 32 + mf * 16 + g + half * 8;
#pragma unroll
                for (int jj = 0; jj < 2; jj++) {
                    int gn = wn * 32 + nf * 8 + 2 * t4 + jj;
                    float v = acc[mf][nf][half * 2 + jj];
                    if (gn < 16)      g_dtin[gm * 16 + gn] = v;
                    else if (gn < 32) bccf[gm * 32 + 2 * (gn - 16)] = v;
                    else if (gn < 48) bccf[gm * 32 + 2 * (gn - 32) + 1] = v;
                }
            }
        }
    }
}

// =====================================================================
// K7: dt_proj GEMM (K=16) + softplus; writes {dt, dt*u} fp16
// =====================================================================
__global__ void k_dtproj(const float* __restrict__ w, const float* __restrict__ dtb) {
    __shared__ float As[16][65];
    __shared__ float Bs[16][65];
    const int m0 = blockIdx.x * 64;
    const int n0 = blockIdx.y * 64;
    const int tid = threadIdx.x;
    const int tx = tid & 15, ty = tid >> 4;
    float acc[4][4] = {};
#pragma unroll
    for (int i = 0; i < 4; i++) {
        int idx = tid + i * 256;
        int m = idx >> 4, kk = idx & 15;
        As[kk][m] = g_dtin[(m0 + m) * 16 + kk];
    }
#pragma unroll
    for (int i = 0; i < 4; i++) {
        int idx = tid + i * 256;
        int n = idx >> 4, kk = idx & 15;
        Bs[kk][n] = w[(n0 + n) * 16 + kk];
    }
    __syncthreads();
#pragma unroll
    for (int kk = 0; kk < 16; kk++) {
        float a[4], c[4];
#pragma unroll
        for (int i = 0; i < 4; i++) a[i] = As[kk][ty * 4 + i];
#pragma unroll
        for (int j = 0; j < 4; j++) c[j] = Bs[kk][tx * 4 + j];
#pragma unroll
        for (int i = 0; i < 4; i++)
#pragma unroll
            for (int j = 0; j < 4; j++) acc[i][j] += a[i] * c[j];
    }
#pragma unroll
    for (int i = 0; i < 4; i++) {
        int gm = m0 + ty * 4 + i;
        uint2 uh = *(const uint2*)&g_uh[gm * 512 + n0 + tx * 4];
        float2 u01 = __half22float2(*(const __half2*)&uh.x);
        float2 u23 = __half22float2(*(const __half2*)&uh.y);
        float um[4] = {u01.x, u01.y, u23.x, u23.y};
#pragma unroll
        for (int j = 0; j < 4; j++) {
            int gn = n0 + tx * 4 + j;
            float x = acc[i][j] + dtb[gn];
            float sp = (x > 20.f) ? x : log1pf(__expf(x));
            g_a[gm * 512 + gn] = __floats2half2_rn(sp, sp * um[j]);
        }
    }
}

// =====================================================================
// K8: scan pass 1 — warp = 4 channels x 8 lanes x 2 states/lane
// =====================================================================
__global__ void __launch_bounds__(256)
k_scan1(const float* __restrict__ alog) {
    const int w    = (blockIdx.x * blockDim.x + threadIdx.x) >> 5;
    const int lane = threadIdx.x & 31;
    const int chunk = w & (NCH - 1);
    const int dq   = (w >> 5) & 127;
    const int b    = w >> 12;
    const int c2 = lane >> 3, s8 = lane & 7;
    const int d  = dq * 4 + c2;
    const int s0 = 2 * s8;
    const float An2a = -__expf(alog[d * 16 + s0])     * LOG2E;
    const float An2b = -__expf(alog[d * 16 + s0 + 1]) * LOG2E;
    float2 h = make_float2(0.f, 0.f);
    float2 P = make_float2(1.f, 1.f);
    const int l0 = chunk * CT_;
    const __half2* ap = g_a + (size_t)(b * LL + l0) * 512 + d;
    const float4*  bp = (const float4*)(g_bcc + (size_t)(b * LL + l0) * 16) + s8;
#pragma unroll 8
    for (int t = 0; t < CT_; t++) {
        float2 av = __half22float2(ap[t * 512]);
        float4 bc = bp[t * 8];
        float dAa = exp2f(av.x * An2a);
        float dAb = exp2f(av.x * An2b);
        h.x = fmaf(dAa, h.x, av.y * bc.x);
        h.y = fmaf(dAb, h.y, av.y * bc.z);
        P.x *= dAa; P.y *= dAb;
    }
    const int tI = (b * 512 + d) * 16 + s0;
    *(float2*)&g_P[chunk * TT_ + tI]  = P;
    *(float2*)&g_Hc[chunk * TT_ + tI] = h;
}

// =====================================================================
// K9: chunk combine — materialize prefix states (coalesced float2)
// =====================================================================
__global__ void k_comb() {
    const int tI = (blockIdx.x * blockDim.x + threadIdx.x) * 2;  // TT_/2 threads
    float2 h = make_float2(0.f, 0.f);
    for (int c = 0; c < NCH; c++) {
        *(float2*)&g_hini[c * TT_ + tI] = h;
        float2 Pv = *(const float2*)&g_P[c * TT_ + tI];
        float2 Hv = *(const float2*)&g_Hc[c * TT_ + tI];
        h.x = Pv.x * h.x + Hv.x;
        h.y = Pv.y * h.y + Hv.y;
    }
}

// =====================================================================
// K10: scan pass 2 — load prefix, replay, y (fp16 out)
// =====================================================================
__global__ void __launch_bounds__(256)
k_scan2(const float* __restrict__ alog, const float* __restrict__ Dp) {
    const int w    = (blockIdx.x * blockDim.x + threadIdx.x) >> 5;
    const int lane = threadIdx.x & 31;
    const int chunk = w & (NCH - 1);
    const int dq   = (w >> 5) & 127;
    const int b    = w >> 12;
    const int c2 = lane >> 3, s8 = lane & 7;
    const int d  = dq * 4 + c2;
    const int s0 = 2 * s8;
    const float An2a = -__expf(alog[d * 16 + s0])     * LOG2E;
    const float An2b = -__expf(alog[d * 16 + s0 + 1]) * LOG2E;
    const float Dv = Dp[d];
    const int tI = (b * 512 + d) * 16 + s0;
    float2 h = *(const float2*)&g_hini[chunk * TT_ + tI];
    const int l0 = chunk * CT_;
    const __half2* ap = g_a  + (size_t)(b * LL + l0) * 512 + d;
    const float4*  bp = (const float4*)(g_bcc + (size_t)(b * LL + l0) * 16) + s8;
    const __half2* up = g_uz + (size_t)(b * LL + l0) * 512 + d;
    __half* yp = g_yfin + (size_t)(b * LL + l0) * 512 + d;
#pragma unroll 4
    for (int t = 0; t < CT_; t++) {
        float2 av = __half22float2(ap[t * 512]);
        float4 bc = bp[t * 8];
        float dAa = exp2f(av.x * An2a);
        float dAb = exp2f(av.x * An2b);
        h.x = fmaf(dAa, h.x, av.y * bc.x);
        h.y = fmaf(dAb, h.y, av.y * bc.z);
        float part = h.x * bc.y + h.y * bc.w;
        part += __shfl_xor_sync(0xffffffffu, part, 1);
        part += __shfl_xor_sync(0xffffffffu, part, 2);
        part += __shfl_xor_sync(0xffffffffu, part, 4);
        if (s8 == 0) {
            float2 uzv = __half22float2(up[t * 512]);
            yp[t * 512] = __float2half((part + uzv.x * Dv) * uzv.y);
        }
    }
}

// =====================================================================
// K11: out_proj GEMM — TF32 TC, fp16 A source, double-buffered,
//      residual + NCHW scatter
// =====================================================================
__global__ void __launch_bounds__(256)
k_outproj_tc(const float* __restrict__ w, float* __restrict__ out) {
    extern __shared__ unsigned dyn[];
    unsigned* As = dyn;
    unsigned* Bs = dyn + 2 * 4608;
    const int m0 = blockIdx.x * 128, n0 = blockIdx.y * 128;
    const int tid = threadIdx.x, lane = tid & 31, wid = tid >> 5;
    const int wm = wid >> 2, wn = wid & 3;
    const int g = lane >> 2, t4 = lane & 3;
    const int r0 = tid >> 3, c4 = tid & 7;
    float acc[4][4][4] = {};
    uint2 ah[4]; float4 bv[4];
#pragma unroll
    for (int i = 0; i < 4; i++) {
        ah[i] = *(const uint2*)&g_yfin[(m0 + r0 + 32 * i) * 512 + c4 * 4];
        bv[i] = *(const float4*)&w[(n0 + r0 + 32 * i) * 512 + c4 * 4];
    }
#pragma unroll
    for (int i = 0; i < 4; i++) {
        int row = r0 + 32 * i;
        float2 f01 = __half22float2(*(const __half2*)&ah[i].x);
        float2 f23 = __half22float2(*(const __half2*)&ah[i].y);
        unsigned* da = &As[row * 36 + c4 * 4];
        da[0] = tf32c(f01.x); da[1] = tf32c(f01.y);
        da[2] = tf32c(f23.x); da[3] = tf32c(f23.y);
        unsigned* db = &Bs[row * 36 + c4 * 4];
        db[0] = tf32c(bv[i].x); db[1] = tf32c(bv[i].y);
        db[2] = tf32c(bv[i].z); db[3] = tf32c(bv[i].w);
    }
    __syncthreads();
    for (int st = 0; st < 16; st++) {
        const unsigned* Ab = As + (st & 1) * 4608;
        const unsigned* Bb = Bs + (st & 1) * 4608;
        if (st < 15) {
            const int k0 = (st + 1) * 32;
#pragma unroll
            for (int i = 0; i < 4; i++) {
                ah[i] = *(const uint2*)&g_yfin[(m0 + r0 + 32 * i) * 512 + k0 + c4 * 4];
                bv[i] = *(const float4*)&w[(n0 + r0 + 32 * i) * 512 + k0 + c4 * 4];
            }
        }
#pragma unroll
        for (int k8 = 0; k8 < 4; k8++) {
            const int kb = k8 * 8;
            unsigned af[4][4], bf[4][2];
#pragma unroll
            for (int mf = 0; mf < 4; mf++) {
                int m = wm * 64 + mf * 16 + g;
                af[mf][0] = Ab[m * 36 + kb + t4];
                af[mf][1] = Ab[(m + 8) * 36 + kb + t4];
                af[mf][2] = Ab[m * 36 + kb + t4 + 4];
                af[mf][3] = Ab[(m + 8) * 36 + kb + t4 + 4];
            }
#pragma unroll
            for (int nf = 0; nf < 4; nf++) {
                int n = wn * 32 + nf * 8 + g;
                bf[nf][0] = Bb[n * 36 + kb + t4];
                bf[nf][1] = Bb[n * 36 + kb + t4 + 4];
            }
#pragma unroll
            for (int mf = 0; mf < 4; mf++)
#pragma unroll
                for (int nf = 0; nf < 4; nf++)
                    mma8(acc[mf][nf], af[mf], bf[nf]);
        }
        if (st < 15) {
            unsigned* Aw = As + ((st + 1) & 1) * 4608;
            unsigned* Bw = Bs + ((st + 1) & 1) * 4608;
#pragma unroll
            for (int i = 0; i < 4; i++) {
                int row = r0 + 32 * i;
                float2 f01 = __half22float2(*(const __half2*)&ah[i].x);
                float2 f23 = __half22float2(*(const __half2*)&ah[i].y);
                unsigned* da = &Aw[row * 36 + c4 * 4];
                da[0] = tf32c(f01.x); da[1] = tf32c(f01.y);
                da[2] = tf32c(f23.x); da[3] = tf32c(f23.y);
                unsigned* db = &Bw[row * 36 + c4 * 4];
                db[0] = tf32c(bv[i].x); db[1] = tf32c(bv[i].y);
                db[2] = tf32c(bv[i].z); db[3] = tf32c(bv[i].w);
            }
            __syncthreads();
        }
    }
    const int bb = m0 >> 12;
#pragma unroll
    for (int mf = 0; mf < 4; mf++) {
        int m = m0 + wm * 64 + mf * 16 + g;
        int l = m & 4095;
#pragma unroll
        for (int nf = 0; nf < 4; nf++) {
            int n = n0 + wn * 32 + nf * 8 + 2 * t4;
            size_t i0 = (size_t)(bb * 256 + n) * 4096 + l;
            size_t i1 = i0 + 4096;
            out[i0]     = acc[mf][nf][0] + g_fused[i0];
            out[i1]     = acc[mf][nf][1] + g_fused[i1];
            out[i0 + 8] = acc[mf][nf][2] + g_fused[i0 + 8];
            out[i1 + 8] = acc[mf][nf][3] + g_fused[i1 + 8];
        }
    }
}

// =====================================================================
extern "C" void kernel_launch(void* const* d_in, const int* in_sizes, int n_in,
                              void* d_out, int out_size) {
    const float* resnet = (const float*)d_in[0];
    const float* scp    = (const float*)d_in[1];
    const float* scpw   = (const float*)d_in[2];
    const float* sg = (const float*)d_in[3];
    const float* sb = (const float*)d_in[4];
    const float* sm = (const float*)d_in[5];
    const float* sv = (const float*)d_in[6];
    const float* rg = (const float*)d_in[7];
    const float* rb = (const float*)d_in[8];
    const float* rm = (const float*)d_in[9];
    const float* rv = (const float*)d_in[10];
    const float* lg = (const float*)d_in[11];
    const float* lb = (const float*)d_in[12];
    const float* inw = (const float*)d_in[13];
    const float* cw  = (const float*)d_in[14];
    const float* cb  = (const float*)d_in[15];
    const float* xw  = (const float*)d_in[16];
    const float* dtw = (const float*)d_in[17];
    const float* dtb = (const float*)d_in[18];
    const float* alog = (const float*)d_in[19];
    const float* Dp   = (const float*)d_in[20];
    const float* ow   = (const float*)d_in[21];
    float* out = (float*)d_out;

    const int DYN = 4 * 4608 * 4;  // 73728 bytes (double-buffered As+Bs)
    cudaFuncSetAttribute(k_inproj_tc, cudaFuncAttributeMaxDynamicSharedMemorySize, DYN);
    cudaFuncSetAttribute(k_outproj_tc, cudaFuncAttributeMaxDynamicSharedMemorySize, DYN);

    k_scp_tc   <<<dim3(2, 8, 2), 256>>>(scp, scpw, sg, sb, sm, sv);
    k_fuse     <<<dim3(128, 8, 2), dim3(32, 8)>>>(resnet, rg, rb, rm, rv);
    k_inproj_tc<<<dim3(64, 8), 256, DYN>>>(inw, lg, lb);
    k_conv4    <<<(NB * LL * DI_) / 1024, 256>>>(cw, cb);
    k_xproj_tc <<<128, 256>>>(xw);
    k_dtproj   <<<dim3(128, 8), 256>>>(dtw, dtb);
    k_scan1    <<<1024, 256>>>(alog);
    k_comb     <<<32, 256>>>();
    k_scan2    <<<1024, 256>>>(alog, Dp);
    k_outproj_tc<<<dim3(64, 2), 256, DYN>>>(ow, out);
}

// round 16
// speedup vs baseline: 1.4500x; 1.0029x over previous
#include <cuda_runtime.h>
#include <cuda_fp16.h>

// ---------------- problem constants ----------------
#define NB   2
#define CR_  256
#define CS_  512
#define LL   4096     // 64*64
#define PS_  1024     // 32*32
#define DI_  512
#define DS_  16
#define NCH  32       // scan chunks
#define CT_  128      // chunk length (NCH*CT_ == LL)
#define TT_  (NB*DI_*DS_)   // 16384 scan tracks
#define EPSF 1e-5f
#define LOG2E 1.4426950408889634f

__device__ __forceinline__ unsigned tf32c(float x) {
    unsigned r; asm("cvt.rna.tf32.f32 %0, %1;" : "=r"(r) : "f"(x)); return r;
}
__device__ __forceinline__ void mma8(float* c, const unsigned* a, const unsigned* b) {
    asm volatile("mma.sync.aligned.m16n8k8.row.col.f32.tf32.tf32.f32 "
        "{%0,%1,%2,%3}, {%4,%5,%6,%7}, {%8,%9}, {%0,%1,%2,%3};"
        : "+f"(c[0]), "+f"(c[1]), "+f"(c[2]), "+f"(c[3])
        : "r"(a[0]), "r"(a[1]), "r"(a[2]), "r"(a[3]), "r"(b[0]), "r"(b[1]));
}

// ---------------- scratch (static device allocs only) ----------------
__device__ float   g_sp   [NB*CR_*PS_];
__device__ float   g_fused[NB*CR_*LL];
__device__ __half  g_xth  [NB*LL*CR_];    // fused transposed, fp16
__device__ float2  g_psum [NB*LL*8];
__device__ __half  g_xmh  [NB*LL*DI_];    // xm fp16
__device__ __half  g_zh   [NB*LL*DI_];    // z fp16
__device__ __half  g_uh   [NB*LL*DI_];    // u fp16
__device__ float   g_dtin [NB*LL*DS_];
__device__ float2  g_bcc  [NB*LL*DS_];    // {B_s, C_s} fp32 interleaved
__device__ __half2 g_a    [NB*LL*DI_];    // {dt, dt*u} fp16
__device__ __half2 g_uz   [NB*LL*DI_];    // {u, silu(z)} fp16
__device__ float   g_P    [NCH*TT_];      // chunk-major, state-pairs contiguous
__device__ float   g_Hc   [NCH*TT_];
__device__ float   g_hini [NCH*TT_];      // materialized chunk-prefix states
__device__ __half  g_yfin [NB*LL*DI_];    // y fp16

// =====================================================================
// K1: scp 1x1 conv GEMM + BN — TF32 TC, B transpose-staged (stride 33)
// =====================================================================
__global__ void __launch_bounds__(256)
k_scp_tc(const float* __restrict__ scp, const float* __restrict__ w,
         const float* __restrict__ gg, const float* __restrict__ bb,
         const float* __restrict__ mm, const float* __restrict__ vv) {
    __shared__ __align__(16) unsigned As[128 * 36];   // W  [o][k]
    __shared__ __align__(16) unsigned Bs[128 * 33];   // scp^T [p][k]
    const int b  = blockIdx.z;
    const int m0 = blockIdx.x * 128;   // o
    const int n0 = blockIdx.y * 128;   // p
    const int tid = threadIdx.x, lane = tid & 31, wid = tid >> 5;
    const int wm = wid >> 2, wn = wid & 3;
    const int g = lane >> 2, t4 = lane & 3;
    const int r0 = tid >> 3, c4 = tid & 7;
    const int kq = tid >> 6, pq2 = (tid & 63) * 2;
    float acc[4][4][4] = {};
    float4 av[4]; float2 bvv[8];
#pragma unroll
    for (int i = 0; i < 4; i++)
        av[i] = *(const float4*)&w[(m0 + r0 + 32 * i) * 512 + c4 * 4];
#pragma unroll
    for (int j = 0; j < 8; j++)
        bvv[j] = *(const float2*)&scp[(b * 512 + j * 4 + kq) * 1024 + n0 + pq2];
    for (int st = 0; st < 16; st++) {
#pragma unroll
        for (int i = 0; i < 4; i++) {
            unsigned* da = &As[(r0 + 32 * i) * 36 + c4 * 4];
            da[0] = tf32c(av[i].x); da[1] = tf32c(av[i].y);
            da[2] = tf32c(av[i].z); da[3] = tf32c(av[i].w);
        }
#pragma unroll
        for (int j = 0; j < 8; j++) {
            Bs[pq2 * 33 + j * 4 + kq]       = tf32c(bvv[j].x);
            Bs[(pq2 + 1) * 33 + j * 4 + kq] = tf32c(bvv[j].y);
        }
        __syncthreads();
        if (st < 15) {
            const int k0 = (st + 1) * 32;
#pragma unroll
            for (int i = 0; i < 4; i++)
                av[i] = *(const float4*)&w[(m0 + r0 + 32 * i) * 512 + k0 + c4 * 4];
#pragma unroll
            for (int j = 0; j < 8; j++)
                bvv[j] = *(const float2*)&scp[(b * 512 + k0 + j * 4 + kq) * 1024 + n0 + pq2];
        }
#pragma unroll
        for (int k8 = 0; k8 < 4; k8++) {
            const int kb = k8 * 8;
            unsigned af[4][4], bf[4][2];
#pragma unroll
            for (int mf = 0; mf < 4; mf++) {
                int m = wm * 64 + mf * 16 + g;
                af[mf][0] = As[m * 36 + kb + t4];
                af[mf][1] = As[(m + 8) * 36 + kb + t4];
                af[mf][2] = As[m * 36 + kb + t4 + 4];
                af[mf][3] = As[(m + 8) * 36 + kb + t4 + 4];
            }
#pragma unroll
            for (int nf = 0; nf < 4; nf++) {
                int n = wn * 32 + nf * 8 + g;
                bf[nf][0] = Bs[n * 33 + kb + t4];
                bf[nf][1] = Bs[n * 33 + kb + t4 + 4];
            }
#pragma unroll
            for (int mf = 0; mf < 4; mf++)
#pragma unroll
                for (int nf = 0; nf < 4; nf++)
                    mma8(acc[mf][nf], af[mf], bf[nf]);
        }
        __syncthreads();
    }
#pragma unroll
    for (int mf = 0; mf < 4; mf++) {
        int o = m0 + wm * 64 + mf * 16 + g;
        float iv0 = gg[o] * rsqrtf(vv[o] + EPSF);
        float be0 = bb[o] - mm[o] * iv0;
        float iv1 = gg[o + 8] * rsqrtf(vv[o + 8] + EPSF);
        float be1 = bb[o + 8] - mm[o + 8] * iv1;
#pragma unroll
        for (int nf = 0; nf < 4; nf++) {
            int p = n0 + wn * 32 + nf * 8 + 2 * t4;
            float* dp  = &g_sp[(b * 256 + o) * 1024 + p];
            float* dp8 = &g_sp[(b * 256 + o + 8) * 1024 + p];
            dp[0]  = acc[mf][nf][0] * iv0 + be0;
            dp[1]  = acc[mf][nf][1] * iv0 + be0;
            dp8[0] = acc[mf][nf][2] * iv1 + be1;
            dp8[1] = acc[mf][nf][3] * iv1 + be1;
        }
    }
}

// =====================================================================
// K2: fused = BN(resnet) + bilinear(sp); (B,C,HW) fp32 + (B,HW,C) fp16
//     + LN psums
// =====================================================================
__global__ void k_fuse(const float* __restrict__ res,
                       const float* __restrict__ rg, const float* __restrict__ rb,
                       const float* __restrict__ rm, const float* __restrict__ rv) {
    __shared__ float tile[32][33];
    const int b  = blockIdx.z;
    const int c0 = blockIdx.y * 32;
    const int l0 = blockIdx.x * 32;
    const int tx = threadIdx.x, ty = threadIdx.y;
    const int l = l0 + tx;
    const int h = l >> 6, wq = l & 63;
    float sh = h * 0.5f - 0.25f;
    float sw = wq * 0.5f - 0.25f;
    int h0 = (int)floorf(sh); float fh = sh - (float)h0;
    int w0 = (int)floorf(sw); float fw = sw - (float)w0;
    int h0c = max(h0, 0), h1c = min(h0 + 1, 31);
    int w0c = max(w0, 0), w1c = min(w0 + 1, 31);
#pragma unroll
    for (int i = 0; i < 4; i++) {
        int c = c0 + ty + i * 8;
        float inv  = rg[c] * rsqrtf(rv[c] + EPSF);
        float beta = rb[c] - rm[c] * inv;
        float val = res[(b * 256 + c) * 4096 + l] * inv + beta;
        const float* spb = g_sp + (b * 256 + c) * 1024;
        float s00 = spb[h0c * 32 + w0c], s01 = spb[h0c * 32 + w1c];
        float s10 = spb[h1c * 32 + w0c], s11 = spb[h1c * 32 + w1c];
        val += (1.f - fh) * ((1.f - fw) * s00 + fw * s01)
             +        fh  * ((1.f - fw) * s10 + fw * s11);
        g_fused[(b * 256 + c) * 4096 + l] = val;
        tile[ty + i * 8][tx] = val;
    }
    __syncthreads();
#pragma unroll
    for (int i = 0; i < 4; i++) {
        int c  = c0 + tx;
        int ll = l0 + ty + i * 8;
        g_xth[(b * 4096 + ll) * 256 + c] = __float2half(tile[tx][ty + i * 8]);
    }
    const int tid = ty * 32 + tx;
    if (tid < 32) {
        float s = 0.f, q = 0.f;
#pragma unroll
        for (int cc = 0; cc < 32; cc++) {
            float v = tile[cc][tid];
            s += v; q += v * v;
        }
        g_psum[(b * 4096 + l0 + tid) * 8 + (c0 >> 5)] = make_float2(s, q);
    }
}

// =====================================================================
// K4: in_proj GEMM — TF32 TC, fp16 A source, double-buffered, fused LN
// =====================================================================
__global__ void __launch_bounds__(256)
k_inproj_tc(const float* __restrict__ w,
            const float* __restrict__ lg, const float* __restrict__ lb) {
    extern __shared__ unsigned dyn[];
    unsigned* As = dyn;             // [2][128*36]
    unsigned* Bs = dyn + 2 * 4608;  // [2][128*36]
    __shared__ float s_mu[128], s_rs[128];
    const int m0 = blockIdx.x * 128, n0 = blockIdx.y * 128;
    const int tid = threadIdx.x, lane = tid & 31, wid = tid >> 5;
    const int wm = wid >> 2, wn = wid & 3;
    const int g = lane >> 2, t4 = lane & 3;
    if (tid < 128) {
        float s = 0.f, qq = 0.f;
#pragma unroll
        for (int i = 0; i < 8; i++) {
            float2 p = g_psum[(m0 + tid) * 8 + i];
            s += p.x; qq += p.y;
        }
        float mu = s * (1.f / 256.f);
        s_mu[tid] = mu;
        s_rs[tid] = rsqrtf(qq * (1.f / 256.f) - mu * mu + EPSF);
    }
    __syncthreads();
    const int r0 = tid >> 3, c4 = tid & 7;
    float mu[4], rs[4];
#pragma unroll
    for (int i = 0; i < 4; i++) { mu[i] = s_mu[r0 + 32 * i]; rs[i] = s_rs[r0 + 32 * i]; }
    float acc[4][4][4] = {};
    uint2 ahx[4]; float4 bv[4], g4, e4;
#pragma unroll
    for (int i = 0; i < 4; i++) {
        ahx[i] = *(const uint2*)&g_xth[(m0 + r0 + 32 * i) * 256 + c4 * 4];
        bv[i]  = *(const float4*)&w[(n0 + r0 + 32 * i) * 256 + c4 * 4];
    }
    g4 = *(const float4*)&lg[c4 * 4];
    e4 = *(const float4*)&lb[c4 * 4];
#pragma unroll
    for (int i = 0; i < 4; i++) {
        int row = r0 + 32 * i;
        float2 f01 = __half22float2(*(const __half2*)&ahx[i].x);
        float2 f23 = __half22float2(*(const __half2*)&ahx[i].y);
        unsigned* da = &As[row * 36 + c4 * 4];
        da[0] = tf32c((f01.x - mu[i]) * rs[i] * g4.x + e4.x);
        da[1] = tf32c((f01.y - mu[i]) * rs[i] * g4.y + e4.y);
        da[2] = tf32c((f23.x - mu[i]) * rs[i] * g4.z + e4.z);
        da[3] = tf32c((f23.y - mu[i]) * rs[i] * g4.w + e4.w);
        unsigned* db = &Bs[row * 36 + c4 * 4];
        db[0] = tf32c(bv[i].x); db[1] = tf32c(bv[i].y);
        db[2] = tf32c(bv[i].z); db[3] = tf32c(bv[i].w);
    }
    __syncthreads();
    for (int st = 0; st < 8; st++) {
        const unsigned* Ab = As + (st & 1) * 4608;
        const unsigned* Bb = Bs + (st & 1) * 4608;
        if (st < 7) {
            const int k0 = (st + 1) * 32;
#pragma unroll
            for (int i = 0; i < 4; i++) {
                ahx[i] = *(const uint2*)&g_xth[(m0 + r0 + 32 * i) * 256 + k0 + c4 * 4];
                bv[i]  = *(const float4*)&w[(n0 + r0 + 32 * i) * 256 + k0 + c4 * 4];
            }
            g4 = *(const float4*)&lg[k0 + c4 * 4];
            e4 = *(const float4*)&lb[k0 + c4 * 4];
        }
#pragma unroll
        for (int k8 = 0; k8 < 4; k8++) {
            const int kb = k8 * 8;
            unsigned af[4][4], bf[4][2];
#pragma unroll
            for (int mf = 0; mf < 4; mf++) {
                int m = wm * 64 + mf * 16 + g;
                af[mf][0] = Ab[m * 36 + kb + t4];
                af[mf][1] = Ab[(m + 8) * 36 + kb + t4];
                af[mf][2] = Ab[m * 36 + kb + t4 + 4];
                af[mf][3] = Ab[(m + 8) * 36 + kb + t4 + 4];
            }
#pragma unroll
            for (int nf = 0; nf < 4; nf++) {
                int n = wn * 32 + nf * 8 + g;
                bf[nf][0] = Bb[n * 36 + kb + t4];
                bf[nf][1] = Bb[n * 36 + kb + t4 + 4];
            }
#pragma unroll
            for (int mf = 0; mf < 4; mf++)
#pragma unroll
                for (int nf = 0; nf < 4; nf++)
                    mma8(acc[mf][nf], af[mf], bf[nf]);
        }
        if (st < 7) {
            unsigned* Aw = As + ((st + 1) & 1) * 4608;
            unsigned* Bw = Bs + ((st + 1) & 1) * 4608;
#pragma unroll
            for (int i = 0; i < 4; i++) {
                int row = r0 + 32 * i;
                float2 f01 = __half22float2(*(const __half2*)&ahx[i].x);
                float2 f23 = __half22float2(*(const __half2*)&ahx[i].y);
                unsigned* da = &Aw[row * 36 + c4 * 4];
                da[0] = tf32c((f01.x - mu[i]) * rs[i] * g4.x + e4.x);
                da[1] = tf32c((f01.y - mu[i]) * rs[i] * g4.y + e4.y);
                da[2] = tf32c((f23.x - mu[i]) * rs[i] * g4.z + e4.z);
                da[3] = tf32c((f23.y - mu[i]) * rs[i] * g4.w + e4.w);
                unsigned* db = &Bw[row * 36 + c4 * 4];
                db[0] = tf32c(bv[i].x); db[1] = tf32c(bv[i].y);
                db[2] = tf32c(bv[i].z); db[3] = tf32c(bv[i].w);
            }
            __syncthreads();
        }
    }
    __half* dsth = (n0 < 512) ? g_xmh : g_zh;
    const int nb = (n0 < 512) ? n0 : (n0 - 512);
#pragma unroll
    for (int mf = 0; mf < 4; mf++) {
        int m = m0 + wm * 64 + mf * 16 + g;
#pragma unroll
        for (int nf = 0; nf < 4; nf++) {
            int n = nb + wn * 32 + nf * 8 + 2 * t4;
            *(__half2*)&dsth[m * 512 + n]       = __floats2half2_rn(acc[mf][nf][0], acc[mf][nf][1]);
            *(__half2*)&dsth[(m + 8) * 512 + n] = __floats2half2_rn(acc[mf][nf][2], acc[mf][nf][3]);
        }
    }
}

// =====================================================================
// K5: causal depthwise conv (k=3) + SiLU -> uh fp16 ; {u, silu(z)} fp16
// =====================================================================
__global__ void k_conv4(const float* __restrict__ cw, const float* __restrict__ cb) {
    const int g = blockIdx.x * blockDim.x + threadIdx.x;
    const int base = g * 4;
    const int d = base & 511;
    const int l = (base >> 9) & 4095;
    uint2 h2 = *(const uint2*)&g_xmh[base];
    float2 x2a = __half22float2(*(const __half2*)&h2.x);
    float2 x2b = __half22float2(*(const __half2*)&h2.y);
    float2 x1a = make_float2(0.f, 0.f), x1b = make_float2(0.f, 0.f);
    float2 x0a = make_float2(0.f, 0.f), x0b = make_float2(0.f, 0.f);
    if (l >= 1) {
        uint2 t = *(const uint2*)&g_xmh[base - 512];
        x1a = __half22float2(*(const __half2*)&t.x);
        x1b = __half22float2(*(const __half2*)&t.y);
    }
    if (l >= 2) {
        uint2 t = *(const uint2*)&g_xmh[base - 1024];
        x0a = __half22float2(*(const __half2*)&t.x);
        x0b = __half22float2(*(const __half2*)&t.y);
    }
    float4 w0 = *(const float4*)&cw[d * 3];
    float4 w1 = *(const float4*)&cw[d * 3 + 4];
    float4 w2 = *(const float4*)&cw[d * 3 + 8];
    float4 cb4 = *(const float4*)&cb[d];
    float f[12] = {w0.x, w0.y, w0.z, w0.w, w1.x, w1.y, w1.z, w1.w, w2.x, w2.y, w2.z, w2.w};
    float a0 = x0a.x * f[0] + x1a.x * f[1]  + x2a.x * f[2]  + cb4.x;
    float a1 = x0a.y * f[3] + x1a.y * f[4]  + x2a.y * f[5]  + cb4.y;
    float a2 = x0b.x * f[6] + x1b.x * f[7]  + x2b.x * f[8]  + cb4.z;
    float a3 = x0b.y * f[9] + x1b.y * f[10] + x2b.y * f[11] + cb4.w;
    float u0 = a0 / (1.f + __expf(-a0));
    float u1 = a1 / (1.f + __expf(-a1));
    float u2 = a2 / (1.f + __expf(-a2));
    float u3 = a3 / (1.f + __expf(-a3));
    uint2 uh;
    *(__half2*)&uh.x = __floats2half2_rn(u0, u1);
    *(__half2*)&uh.y = __floats2half2_rn(u2, u3);
    *(uint2*)&g_uh[base] = uh;
    uint2 zh = *(const uint2*)&g_zh[base];
    float2 z01 = __half22float2(*(const __half2*)&zh.x);
    float2 z23 = __half22float2(*(const __half2*)&zh.y);
    uint4 uz;
    *(__half2*)&uz.x = __floats2half2_rn(u0, z01.x / (1.f + __expf(-z01.x)));
    *(__half2*)&uz.y = __floats2half2_rn(u1, z01.y / (1.f + __expf(-z01.y)));
    *(__half2*)&uz.z = __floats2half2_rn(u2, z23.x / (1.f + __expf(-z23.x)));
    *(__half2*)&uz.w = __floats2half2_rn(u3, z23.y / (1.f + __expf(-z23.y)));
    *(uint4*)&g_uz[base] = uz;
}

// =====================================================================
// K6: x_proj GEMM — TF32 TC 128x64 (48 live cols), fp16 A source
// =====================================================================
__global__ void __launch_bounds__(256)
k_xproj_tc(const float* __restrict__ w) {
    __shared__ __align__(16) unsigned As[128 * 36];
    __shared__ __align__(16) unsigned Bs[64 * 36];
    const int m0 = blockIdx.x * 128;
    const int tid = threadIdx.x, lane = tid & 31, wid = tid >> 5;
    const int wm = wid >> 1, wn = wid & 1;
    const int g = lane >> 2, t4 = lane & 3;
    const int r0 = tid >> 3, c4 = tid & 7;
    float acc[2][4][4] = {};
    uint2 ah[4]; float4 bv[2];
#pragma unroll
    for (int i = 0; i < 4; i++)
        ah[i] = *(const uint2*)&g_uh[(m0 + r0 + 32 * i) * 512 + c4 * 4];
#pragma unroll
    for (int i = 0; i < 2; i++) {
        int n = r0 + 32 * i;
        bv[i] = (n < 48) ? *(const float4*)&w[n * 512 + c4 * 4]
                         : make_float4(0.f, 0.f, 0.f, 0.f);
    }
    for (int st = 0; st < 16; st++) {
#pragma unroll
        for (int i = 0; i < 4; i++) {
            float2 f01 = __half22float2(*(const __half2*)&ah[i].x);
            float2 f23 = __half22float2(*(const __half2*)&ah[i].y);
            unsigned* da = &As[(r0 + 32 * i) * 36 + c4 * 4];
            da[0] = tf32c(f01.x); da[1] = tf32c(f01.y);
            da[2] = tf32c(f23.x); da[3] = tf32c(f23.y);
        }
#pragma unroll
        for (int i = 0; i < 2; i++) {
            unsigned* db = &Bs[(r0 + 32 * i) * 36 + c4 * 4];
            db[0] = tf32c(bv[i].x); db[1] = tf32c(bv[i].y);
            db[2] = tf32c(bv[i].z); db[3] = tf32c(bv[i].w);
        }
        __syncthreads();
        if (st < 15) {
            const int k0 = (st + 1) * 32;
#pragma unroll
            for (int i = 0; i < 4; i++)
                ah[i] = *(const uint2*)&g_uh[(m0 + r0 + 32 * i) * 512 + k0 + c4 * 4];
#pragma unroll
            for (int i = 0; i < 2; i++) {
                int n = r0 + 32 * i;
                bv[i] = (n < 48) ? *(const float4*)&w[n * 512 + k0 + c4 * 4]
                                 : make_float4(0.f, 0.f, 0.f, 0.f);
            }
        }
#pragma unroll
        for (int k8 = 0; k8 < 4; k8++) {
            const int kb = k8 * 8;
            unsigned af[2][4], bf[4][2];
#pragma unroll
            for (int mf = 0; mf < 2; mf++) {
                int m = wm * 32 + mf * 16 + g;
                af[mf][0] = As[m * 36 + kb + t4];
                af[mf][1] = As[(m + 8) * 36 + kb + t4];
                af[mf][2] = As[m * 36 + kb + t4 + 4];
                af[mf][3] = As[(m + 8) * 36 + kb + t4 + 4];
            }
#pragma unroll
            for (int nf = 0; nf < 4; nf++) {
                int n = wn * 32 + nf * 8 + g;
                bf[nf][0] = Bs[n * 36 + kb + t4];
                bf[nf][1] = Bs[n * 36 + kb + t4 + 4];
            }
#pragma unroll
            for (int mf = 0; mf < 2; mf++)
#pragma unroll
                for (int nf = 0; nf < 4; nf++)
                    mma8(acc[mf][nf], af[mf], bf[nf]);
        }
        __syncthreads();
    }
    float* bccf = (float*)g_bcc;
#pragma unroll
    for (int mf = 0; mf < 2; mf++) {
#pragma unroll
        for (int nf = 0; nf < 4; nf++) {
#pragma unroll
            for (int half = 0; half < 2; half++) {
                int gm = m0 + wm * 32 + mf * 16 + g + half * 8;
#pragma unroll
                for (int jj = 0; jj < 2; jj++) {
                    int gn = wn * 32 + nf * 8 + 2 * t4 + jj;
                    float v = acc[mf][nf][half * 2 + jj];
                    if (gn < 16)      g_dtin[gm * 16 + gn] = v;
                    else if (gn < 32) bccf[gm * 32 + 2 * (gn - 16)] = v;
                    else if (gn < 48) bccf[gm * 32 + 2 * (gn - 32) + 1] = v;
                }
            }
        }
    }
}

// =====================================================================
// K7: dt_proj GEMM (K=16) + softplus; writes {dt, dt*u} fp16
// =====================================================================
__global__ void k_dtproj(const float* __restrict__ w, const float* __restrict__ dtb) {
    __shared__ float As[16][65];
    __shared__ float Bs[16][65];
    const int m0 = blockIdx.x * 64;
    const int n0 = blockIdx.y * 64;
    const int tid = threadIdx.x;
    const int tx = tid & 15, ty = tid >> 4;
    float acc[4][4] = {};
#pragma unroll
    for (int i = 0; i < 4; i++) {
        int idx = tid + i * 256;
        int m = idx >> 4, kk = idx & 15;
        As[kk][m] = g_dtin[(m0 + m) * 16 + kk];
    }
#pragma unroll
    for (int i = 0; i < 4; i++) {
        int idx = tid + i * 256;
        int n = idx >> 4, kk = idx & 15;
        Bs[kk][n] = w[(n0 + n) * 16 + kk];
    }
    __syncthreads();
#pragma unroll
    for (int kk = 0; kk < 16; kk++) {
        float a[4], c[4];
#pragma unroll
        for (int i = 0; i < 4; i++) a[i] = As[kk][ty * 4 + i];
#pragma unroll
        for (int j = 0; j < 4; j++) c[j] = Bs[kk][tx * 4 + j];
#pragma unroll
        for (int i = 0; i < 4; i++)
#pragma unroll
            for (int j = 0; j < 4; j++) acc[i][j] += a[i] * c[j];
    }
#pragma unroll
    for (int i = 0; i < 4; i++) {
        int gm = m0 + ty * 4 + i;
        uint2 uh = *(const uint2*)&g_uh[gm * 512 + n0 + tx * 4];
        float2 u01 = __half22float2(*(const __half2*)&uh.x);
        float2 u23 = __half22float2(*(const __half2*)&uh.y);
        float um[4] = {u01.x, u01.y, u23.x, u23.y};
#pragma unroll
        for (int j = 0; j < 4; j++) {
            int gn = n0 + tx * 4 + j;
            float x = acc[i][j] + dtb[gn];
            float sp = (x > 20.f) ? x : log1pf(__expf(x));
            g_a[gm * 512 + gn] = __floats2half2_rn(sp, sp * um[j]);
        }
    }
}

// =====================================================================
// K8: scan pass 1 — warp = 4 channels x 8 lanes x 2 states/lane
// =====================================================================
__global__ void __launch_bounds__(256)
k_scan1(const float* __restrict__ alog) {
    const int w    = (blockIdx.x * blockDim.x + threadIdx.x) >> 5;
    const int lane = threadIdx.x & 31;
    const int chunk = w & (NCH - 1);
    const int dq   = (w >> 5) & 127;
    const int b    = w >> 12;
    const int c2 = lane >> 3, s8 = lane & 7;
    const int d  = dq * 4 + c2;
    const int s0 = 2 * s8;
    const float An2a = -__expf(alog[d * 16 + s0])     * LOG2E;
    const float An2b = -__expf(alog[d * 16 + s0 + 1]) * LOG2E;
    float2 h = make_float2(0.f, 0.f);
    float2 P = make_float2(1.f, 1.f);
    const int l0 = chunk * CT_;
    const __half2* ap = g_a + (size_t)(b * LL + l0) * 512 + d;
    const float4*  bp = (const float4*)(g_bcc + (size_t)(b * LL + l0) * 16) + s8;
#pragma unroll 8
    for (int t = 0; t < CT_; t++) {
        float2 av = __half22float2(ap[t * 512]);
        float4 bc = bp[t * 8];
        float dAa = exp2f(av.x * An2a);
        float dAb = exp2f(av.x * An2b);
        h.x = fmaf(dAa, h.x, av.y * bc.x);
        h.y = fmaf(dAb, h.y, av.y * bc.z);
        P.x *= dAa; P.y *= dAb;
    }
    const int tI = (b * 512 + d) * 16 + s0;
    *(float2*)&g_P[chunk * TT_ + tI]  = P;
    *(float2*)&g_Hc[chunk * TT_ + tI] = h;
}

// =====================================================================
// K9: chunk combine — materialize prefix states (coalesced float2)
// =====================================================================
__global__ void k_comb() {
    const int tI = (blockIdx.x * blockDim.x + threadIdx.x) * 2;  // TT_/2 threads
    float2 h = make_float2(0.f, 0.f);
    for (int c = 0; c < NCH; c++) {
        *(float2*)&g_hini[c * TT_ + tI] = h;
        float2 Pv = *(const float2*)&g_P[c * TT_ + tI];
        float2 Hv = *(const float2*)&g_Hc[c * TT_ + tI];
        h.x = Pv.x * h.x + Hv.x;
        h.y = Pv.y * h.y + Hv.y;
    }
}

// =====================================================================
// K10: scan pass 2 — load prefix, replay, y (fp16 out)
// =====================================================================
__global__ void __launch_bounds__(256)
k_scan2(const float* __restrict__ alog, const float* __restrict__ Dp) {
    const int w    = (blockIdx.x * blockDim.x + threadIdx.x) >> 5;
    const int lane = threadIdx.x & 31;
    const int chunk = w & (NCH - 1);
    const int dq   = (w >> 5) & 127;
    const int b    = w >> 12;
    const int c2 = lane >> 3, s8 = lane & 7;
    const int d  = dq * 4 + c2;
    const int s0 = 2 * s8;
    const float An2a = -__expf(alog[d * 16 + s0])     * LOG2E;
    const float An2b = -__expf(alog[d * 16 + s0 + 1]) * LOG2E;
    const float Dv = Dp[d];
    const int tI = (b * 512 + d) * 16 + s0;
    float2 h = *(const float2*)&g_hini[chunk * TT_ + tI];
    const int l0 = chunk * CT_;
    const __half2* ap = g_a  + (size_t)(b * LL + l0) * 512 + d;
    const float4*  bp = (const float4*)(g_bcc + (size_t)(b * LL + l0) * 16) + s8;
    const __half2* up = g_uz + (size_t)(b * LL + l0) * 512 + d;
    __half* yp = g_yfin + (size_t)(b * LL + l0) * 512 + d;
#pragma unroll 4
    for (int t = 0; t < CT_; t++) {
        float2 av = __half22float2(ap[t * 512]);
        float4 bc = bp[t * 8];
        float dAa = exp2f(av.x * An2a);
        float dAb = exp2f(av.x * An2b);
        h.x = fmaf(dAa, h.x, av.y * bc.x);
        h.y = fmaf(dAb, h.y, av.y * bc.z);
        float part = h.x * bc.y + h.y * bc.w;
        part += __shfl_xor_sync(0xffffffffu, part, 1);
        part += __shfl_xor_sync(0xffffffffu, part, 2);
        part += __shfl_xor_sync(0xffffffffu, part, 4);
        if (s8 == 0) {
            float2 uzv = __half22float2(up[t * 512]);
            yp[t * 512] = __float2half((part + uzv.x * Dv) * uzv.y);
        }
    }
}

// =====================================================================
// K11: out_proj GEMM — TF32 TC, fp16 A source, double-buffered,
//      residual + NCHW scatter
// =====================================================================
__global__ void __launch_bounds__(256)
k_outproj_tc(const float* __restrict__ w, float* __restrict__ out) {
    extern __shared__ unsigned dyn[];
    unsigned* As = dyn;
    unsigned* Bs = dyn + 2 * 4608;
    const int m0 = blockIdx.x * 128, n0 = blockIdx.y * 128;
    const int tid = threadIdx.x, lane = tid & 31, wid = tid >> 5;
    const int wm = wid >> 2, wn = wid & 3;
    const int g = lane >> 2, t4 = lane & 3;
    const int r0 = tid >> 3, c4 = tid & 7;
    float acc[4][4][4] = {};
    uint2 ah[4]; float4 bv[4];
#pragma unroll
    for (int i = 0; i < 4; i++) {
        ah[i] = *(const uint2*)&g_yfin[(m0 + r0 + 32 * i) * 512 + c4 * 4];
        bv[i] = *(const float4*)&w[(n0 + r0 + 32 * i) * 512 + c4 * 4];
    }
#pragma unroll
    for (int i = 0; i < 4; i++) {
        int row = r0 + 32 * i;
        float2 f01 = __half22float2(*(const __half2*)&ah[i].x);
        float2 f23 = __half22float2(*(const __half2*)&ah[i].y);
        unsigned* da = &As[row * 36 + c4 * 4];
        da[0] = tf32c(f01.x); da[1] = tf32c(f01.y);
        da[2] = tf32c(f23.x); da[3] = tf32c(f23.y);
        unsigned* db = &Bs[row * 36 + c4 * 4];
        db[0] = tf32c(bv[i].x); db[1] = tf32c(bv[i].y);
        db[2] = tf32c(bv[i].z); db[3] = tf32c(bv[i].w);
    }
    __syncthreads();
    for (int st = 0; st < 16; st++) {
        const unsigned* Ab = As + (st & 1) * 4608;
        const unsigned* Bb = Bs + (st & 1) * 4608;
        if (st < 15) {
            const int k0 = (st + 1) * 32;
#pragma unroll
            for (int i = 0; i < 4; i++) {
                ah[i] = *(const uint2*)&g_yfin[(m0 + r0 + 32 * i) * 512 + k0 + c4 * 4];
                bv[i] = *(const float4*)&w[(n0 + r0 + 32 * i) * 512 + k0 + c4 * 4];
            }
        }
#pragma unroll
        for (int k8 = 0; k8 < 4; k8++) {
            const int kb = k8 * 8;
            unsigned af[4][4], bf[4][2];
#pragma unroll
            for (int mf = 0; mf < 4; mf++) {
                int m = wm * 64 + mf * 16 + g;
                af[mf][0] = Ab[m * 36 + kb + t4];
                af[mf][1] = Ab[(m + 8) * 36 + kb + t4];
                af[mf][2] = Ab[m * 36 + kb + t4 + 4];
                af[mf][3] = Ab[(m + 8) * 36 + kb + t4 + 4];
            }
#pragma unroll
            for (int nf = 0; nf < 4; nf++) {
                int n = wn * 32 + nf * 8 + g;
                bf[nf][0] = Bb[n * 36 + kb + t4];
                bf[nf][1] = Bb[n * 36 + kb + t4 + 4];
            }
#pragma unroll
            for (int mf = 0; mf < 4; mf++)
#pragma unroll
                for (int nf = 0; nf < 4; nf++)
                    mma8(acc[mf][nf], af[mf], bf[nf]);
        }
        if (st < 15) {
            unsigned* Aw = As + ((st + 1) & 1) * 4608;
            unsigned* Bw = Bs + ((st + 1) & 1) * 4608;
#pragma unroll
            for (int i = 0; i < 4; i++) {
                int row = r0 + 32 * i;
                float2 f01 = __half22float2(*(const __half2*)&ah[i].x);
                float2 f23 = __half22float2(*(const __half2*)&ah[i].y);
                unsigned* da = &Aw[row * 36 + c4 * 4];
                da[0] = tf32c(f01.x); da[1] = tf32c(f01.y);
                da[2] = tf32c(f23.x); da[3] = tf32c(f23.y);
                unsigned* db = &Bw[row * 36 + c4 * 4];
                db[0] = tf32c(bv[i].x); db[1] = tf32c(bv[i].y);
                db[2] = tf32c(bv[i].z); db[3] = tf32c(bv[i].w);
            }
            __syncthreads();
        }
    }
    const int bb = m0 >> 12;
#pragma unroll
    for (int mf = 0; mf < 4; mf++) {
        int m = m0 + wm * 64 + mf * 16 + g;
        int l = m & 4095;
#pragma unroll
        for (int nf = 0; nf < 4; nf++) {
            int n = n0 + wn * 32 + nf * 8 + 2 * t4;
            size_t i0 = (size_t)(bb * 256 + n) * 4096 + l;
            size_t i1 = i0 + 4096;
            out[i0]     = acc[mf][nf][0] + g_fused[i0];
            out[i1]     = acc[mf][nf][1] + g_fused[i1];
            out[i0 + 8] = acc[mf][nf][2] + g_fused[i0 + 8];
            out[i1 + 8] = acc[mf][nf][3] + g_fused[i1 + 8];
        }
    }
}

// =====================================================================
extern "C" void kernel_launch(void* const* d_in, const int* in_sizes, int n_in,
                              void* d_out, int out_size) {
    const float* resnet = (const float*)d_in[0];
    const float* scp    = (const float*)d_in[1];
    const float* scpw   = (const float*)d_in[2];
    const float* sg = (const float*)d_in[3];
    const float* sb = (const float*)d_in[4];
    const float* sm = (const float*)d_in[5];
    const float* sv = (const float*)d_in[6];
    const float* rg = (const float*)d_in[7];
    const float* rb = (const float*)d_in[8];
    const float* rm = (const float*)d_in[9];
    const float* rv = (const float*)d_in[10];
    const float* lg = (const float*)d_in[11];
    const float* lb = (const float*)d_in[12];
    const float* inw = (const float*)d_in[13];
    const float* cw  = (const float*)d_in[14];
    const float* cb  = (const float*)d_in[15];
    const float* xw  = (const float*)d_in[16];
    const float* dtw = (const float*)d_in[17];
    const float* dtb = (const float*)d_in[18];
    const float* alog = (const float*)d_in[19];
    const float* Dp   = (const float*)d_in[20];
    const float* ow   = (const float*)d_in[21];
    float* out = (float*)d_out;

    const int DYN = 4 * 4608 * 4;  // 73728 bytes (double-buffered As+Bs)
    cudaFuncSetAttribute(k_inproj_tc, cudaFuncAttributeMaxDynamicSharedMemorySize, DYN);
    cudaFuncSetAttribute(k_outproj_tc, cudaFuncAttributeMaxDynamicSharedMemorySize, DYN);

    k_scp_tc   <<<dim3(2, 8, 2), 256>>>(scp, scpw, sg, sb, sm, sv);
    k_fuse     <<<dim3(128, 8, 2), dim3(32, 8)>>>(resnet, rg, rb, rm, rv);
    k_inproj_tc<<<dim3(64, 8), 256, DYN>>>(inw, lg, lb);
    k_conv4    <<<(NB * LL * DI_) / 1024, 256>>>(cw, cb);
    k_xproj_tc <<<64, 256>>>(xw);
    k_dtproj   <<<dim3(128, 8), 256>>>(dtw, dtb);
    k_scan1    <<<1024, 256>>>(alog);
    k_comb     <<<32, 256>>>();
    k_scan2    <<<1024, 256>>>(alog, Dp);
    k_outproj_tc<<<dim3(64, 2), 256, DYN>>>(ow, out);
}

// round 17
// speedup vs baseline: 1.4906x; 1.0280x over previous
#include <cuda_runtime.h>
#include <cuda_fp16.h>

// ---------------- problem constants ----------------
#define NB   2
#define CR_  256
#define CS_  512
#define LL   4096     // 64*64
#define PS_  1024     // 32*32
#define DI_  512
#define DS_  16
#define NCH  32       // scan chunks
#define CT_  128      // chunk length (NCH*CT_ == LL)
#define TT_  (NB*DI_*DS_)   // 16384 scan tracks
#define EPSF 1e-5f
#define LOG2E 1.4426950408889634f

__device__ __forceinline__ unsigned tf32c(float x) {
    unsigned r; asm("cvt.rna.tf32.f32 %0, %1;" : "=r"(r) : "f"(x)); return r;
}
__device__ __forceinline__ void mma8(float* c, const unsigned* a, const unsigned* b) {
    asm volatile("mma.sync.aligned.m16n8k8.row.col.f32.tf32.tf32.f32 "
        "{%0,%1,%2,%3}, {%4,%5,%6,%7}, {%8,%9}, {%0,%1,%2,%3};"
        : "+f"(c[0]), "+f"(c[1]), "+f"(c[2]), "+f"(c[3])
        : "r"(a[0]), "r"(a[1]), "r"(a[2]), "r"(a[3]), "r"(b[0]), "r"(b[1]));
}
__device__ __forceinline__ void mma16h(float* c, const unsigned* a, const unsigned* b) {
    asm volatile("mma.sync.aligned.m16n8k16.row.col.f32.f16.f16.f32 "
        "{%0,%1,%2,%3}, {%4,%5,%6,%7}, {%8,%9}, {%0,%1,%2,%3};"
        : "+f"(c[0]), "+f"(c[1]), "+f"(c[2]), "+f"(c[3])
        : "r"(a[0]), "r"(a[1]), "r"(a[2]), "r"(a[3]), "r"(b[0]), "r"(b[1]));
}
__device__ __forceinline__ unsigned h2pack(float lo, float hi) {
    __half2 h = __floats2half2_rn(lo, hi);
    return *(unsigned*)&h;
}

// ---------------- scratch (static device allocs only) ----------------
__device__ float   g_sp   [NB*CR_*PS_];
__device__ float   g_fused[NB*CR_*LL];
__device__ __half  g_xth  [NB*LL*CR_];    // fused transposed, fp16
__device__ float2  g_psum [NB*LL*8];
__device__ __half  g_xmh  [NB*LL*DI_];    // xm fp16
__device__ __half  g_zh   [NB*LL*DI_];    // z fp16
__device__ __half  g_uh   [NB*LL*DI_];    // u fp16
__device__ float   g_dtin [NB*LL*DS_];
__device__ float2  g_bcc  [NB*LL*DS_];    // {B_s, C_s} fp32 interleaved
__device__ __half2 g_a    [NB*LL*DI_];    // {dt, dt*u} fp16
__device__ __half2 g_uz   [NB*LL*DI_];    // {u, silu(z)} fp16
__device__ float   g_P    [NCH*TT_];      // chunk-major, state-pairs contiguous
__device__ float   g_Hc   [NCH*TT_];
__device__ float   g_hini [NCH*TT_];      // materialized chunk-prefix states
__device__ __half  g_yfin [NB*LL*DI_];    // y fp16

// =====================================================================
// K1: scp 1x1 conv GEMM + BN — TF32 TC, B transpose-staged (stride 33)
// =====================================================================
__global__ void __launch_bounds__(256)
k_scp_tc(const float* __restrict__ scp, const float* __restrict__ w,
         const float* __restrict__ gg, const float* __restrict__ bb,
         const float* __restrict__ mm, const float* __restrict__ vv) {
    __shared__ __align__(16) unsigned As[128 * 36];   // W  [o][k]
    __shared__ __align__(16) unsigned Bs[128 * 33];   // scp^T [p][k]
    const int b  = blockIdx.z;
    const int m0 = blockIdx.x * 128;   // o
    const int n0 = blockIdx.y * 128;   // p
    const int tid = threadIdx.x, lane = tid & 31, wid = tid >> 5;
    const int wm = wid >> 2, wn = wid & 3;
    const int g = lane >> 2, t4 = lane & 3;
    const int r0 = tid >> 3, c4 = tid & 7;
    const int kq = tid >> 6, pq2 = (tid & 63) * 2;
    float acc[4][4][4] = {};
    float4 av[4]; float2 bvv[8];
#pragma unroll
    for (int i = 0; i < 4; i++)
        av[i] = *(const float4*)&w[(m0 + r0 + 32 * i) * 512 + c4 * 4];
#pragma unroll
    for (int j = 0; j < 8; j++)
        bvv[j] = *(const float2*)&scp[(b * 512 + j * 4 + kq) * 1024 + n0 + pq2];
    for (int st = 0; st < 16; st++) {
#pragma unroll
        for (int i = 0; i < 4; i++) {
            unsigned* da = &As[(r0 + 32 * i) * 36 + c4 * 4];
            da[0] = tf32c(av[i].x); da[1] = tf32c(av[i].y);
            da[2] = tf32c(av[i].z); da[3] = tf32c(av[i].w);
        }
#pragma unroll
        for (int j = 0; j < 8; j++) {
            Bs[pq2 * 33 + j * 4 + kq]       = tf32c(bvv[j].x);
            Bs[(pq2 + 1) * 33 + j * 4 + kq] = tf32c(bvv[j].y);
        }
        __syncthreads();
        if (st < 15) {
            const int k0 = (st + 1) * 32;
#pragma unroll
            for (int i = 0; i < 4; i++)
                av[i] = *(const float4*)&w[(m0 + r0 + 32 * i) * 512 + k0 + c4 * 4];
#pragma unroll
            for (int j = 0; j < 8; j++)
                bvv[j] = *(const float2*)&scp[(b * 512 + k0 + j * 4 + kq) * 1024 + n0 + pq2];
        }
#pragma unroll
        for (int k8 = 0; k8 < 4; k8++) {
            const int kb = k8 * 8;
            unsigned af[4][4], bf[4][2];
#pragma unroll
            for (int mf = 0; mf < 4; mf++) {
                int m = wm * 64 + mf * 16 + g;
                af[mf][0] = As[m * 36 + kb + t4];
                af[mf][1] = As[(m + 8) * 36 + kb + t4];
                af[mf][2] = As[m * 36 + kb + t4 + 4];
                af[mf][3] = As[(m + 8) * 36 + kb + t4 + 4];
            }
#pragma unroll
            for (int nf = 0; nf < 4; nf++) {
                int n = wn * 32 + nf * 8 + g;
                bf[nf][0] = Bs[n * 33 + kb + t4];
                bf[nf][1] = Bs[n * 33 + kb + t4 + 4];
            }
#pragma unroll
            for (int mf = 0; mf < 4; mf++)
#pragma unroll
                for (int nf = 0; nf < 4; nf++)
                    mma8(acc[mf][nf], af[mf], bf[nf]);
        }
        __syncthreads();
    }
#pragma unroll
    for (int mf = 0; mf < 4; mf++) {
        int o = m0 + wm * 64 + mf * 16 + g;
        float iv0 = gg[o] * rsqrtf(vv[o] + EPSF);
        float be0 = bb[o] - mm[o] * iv0;
        float iv1 = gg[o + 8] * rsqrtf(vv[o + 8] + EPSF);
        float be1 = bb[o + 8] - mm[o + 8] * iv1;
#pragma unroll
        for (int nf = 0; nf < 4; nf++) {
            int p = n0 + wn * 32 + nf * 8 + 2 * t4;
            float* dp  = &g_sp[(b * 256 + o) * 1024 + p];
            float* dp8 = &g_sp[(b * 256 + o + 8) * 1024 + p];
            dp[0]  = acc[mf][nf][0] * iv0 + be0;
            dp[1]  = acc[mf][nf][1] * iv0 + be0;
            dp8[0] = acc[mf][nf][2] * iv1 + be1;
            dp8[1] = acc[mf][nf][3] * iv1 + be1;
        }
    }
}

// =====================================================================
// K2: fused = BN(resnet) + bilinear(sp); (B,C,HW) fp32 + (B,HW,C) fp16
//     + LN psums
// =====================================================================
__global__ void k_fuse(const float* __restrict__ res,
                       const float* __restrict__ rg, const float* __restrict__ rb,
                       const float* __restrict__ rm, const float* __restrict__ rv) {
    __shared__ float tile[32][33];
    const int b  = blockIdx.z;
    const int c0 = blockIdx.y * 32;
    const int l0 = blockIdx.x * 32;
    const int tx = threadIdx.x, ty = threadIdx.y;
    const int l = l0 + tx;
    const int h = l >> 6, wq = l & 63;
    float sh = h * 0.5f - 0.25f;
    float sw = wq * 0.5f - 0.25f;
    int h0 = (int)floorf(sh); float fh = sh - (float)h0;
    int w0 = (int)floorf(sw); float fw = sw - (float)w0;
    int h0c = max(h0, 0), h1c = min(h0 + 1, 31);
    int w0c = max(w0, 0), w1c = min(w0 + 1, 31);
#pragma unroll
    for (int i = 0; i < 4; i++) {
        int c = c0 + ty + i * 8;
        float inv  = rg[c] * rsqrtf(rv[c] + EPSF);
        float beta = rb[c] - rm[c] * inv;
        float val = res[(b * 256 + c) * 4096 + l] * inv + beta;
        const float* spb = g_sp + (b * 256 + c) * 1024;
        float s00 = spb[h0c * 32 + w0c], s01 = spb[h0c * 32 + w1c];
        float s10 = spb[h1c * 32 + w0c], s11 = spb[h1c * 32 + w1c];
        val += (1.f - fh) * ((1.f - fw) * s00 + fw * s01)
             +        fh  * ((1.f - fw) * s10 + fw * s11);
        g_fused[(b * 256 + c) * 4096 + l] = val;
        tile[ty + i * 8][tx] = val;
    }
    __syncthreads();
#pragma unroll
    for (int i = 0; i < 4; i++) {
        int c  = c0 + tx;
        int ll = l0 + ty + i * 8;
        g_xth[(b * 4096 + ll) * 256 + c] = __float2half(tile[tx][ty + i * 8]);
    }
    const int tid = ty * 32 + tx;
    if (tid < 32) {
        float s = 0.f, q = 0.f;
#pragma unroll
        for (int cc = 0; cc < 32; cc++) {
            float v = tile[cc][tid];
            s += v; q += v * v;
        }
        g_psum[(b * 4096 + l0 + tid) * 8 + (c0 >> 5)] = make_float2(s, q);
    }
}

// =====================================================================
// K4: in_proj GEMM — FP16 MMA (m16n8k16, fp32 accum), fp16 A source,
//     double-buffered, fused LN. Stride-18 half2 smem rows.
// =====================================================================
__global__ void __launch_bounds__(256)
k_inproj_tc(const float* __restrict__ w,
            const float* __restrict__ lg, const float* __restrict__ lb) {
    extern __shared__ unsigned dyn[];
    unsigned* As = dyn;             // [2][128*18] half2 words
    unsigned* Bs = dyn + 2 * 2304;  // [2][128*18]
    __shared__ float s_mu[128], s_rs[128];
    const int m0 = blockIdx.x * 128, n0 = blockIdx.y * 128;
    const int tid = threadIdx.x, lane = tid & 31, wid = tid >> 5;
    const int wm = wid >> 2, wn = wid & 3;
    const int g = lane >> 2, t4 = lane & 3;
    if (tid < 128) {
        float s = 0.f, qq = 0.f;
#pragma unroll
        for (int i = 0; i < 8; i++) {
            float2 p = g_psum[(m0 + tid) * 8 + i];
            s += p.x; qq += p.y;
        }
        float mu = s * (1.f / 256.f);
        s_mu[tid] = mu;
        s_rs[tid] = rsqrtf(qq * (1.f / 256.f) - mu * mu + EPSF);
    }
    __syncthreads();
    const int r0 = tid >> 3, c4 = tid & 7;   // c4: k-halves group (4 halves)
    float mu[4], rs[4];
#pragma unroll
    for (int i = 0; i < 4; i++) { mu[i] = s_mu[r0 + 32 * i]; rs[i] = s_rs[r0 + 32 * i]; }
    float acc[4][4][4] = {};
    uint2 ahx[4]; float4 bv[4], g4, e4;
#pragma unroll
    for (int i = 0; i < 4; i++) {
        ahx[i] = *(const uint2*)&g_xth[(m0 + r0 + 32 * i) * 256 + c4 * 4];
        bv[i]  = *(const float4*)&w[(n0 + r0 + 32 * i) * 256 + c4 * 4];
    }
    g4 = *(const float4*)&lg[c4 * 4];
    e4 = *(const float4*)&lb[c4 * 4];
#pragma unroll
    for (int i = 0; i < 4; i++) {
        int row = r0 + 32 * i;
        float2 f01 = __half22float2(*(const __half2*)&ahx[i].x);
        float2 f23 = __half22float2(*(const __half2*)&ahx[i].y);
        unsigned* da = &As[row * 18 + c4 * 2];
        da[0] = h2pack((f01.x - mu[i]) * rs[i] * g4.x + e4.x,
                       (f01.y - mu[i]) * rs[i] * g4.y + e4.y);
        da[1] = h2pack((f23.x - mu[i]) * rs[i] * g4.z + e4.z,
                       (f23.y - mu[i]) * rs[i] * g4.w + e4.w);
        unsigned* db = &Bs[row * 18 + c4 * 2];
        db[0] = h2pack(bv[i].x, bv[i].y);
        db[1] = h2pack(bv[i].z, bv[i].w);
    }
    __syncthreads();
    for (int st = 0; st < 8; st++) {
        const unsigned* Ab = As + (st & 1) * 2304;
        const unsigned* Bb = Bs + (st & 1) * 2304;
        if (st < 7) {
            const int k0 = (st + 1) * 32;
#pragma unroll
            for (int i = 0; i < 4; i++) {
                ahx[i] = *(const uint2*)&g_xth[(m0 + r0 + 32 * i) * 256 + k0 + c4 * 4];
                bv[i]  = *(const float4*)&w[(n0 + r0 + 32 * i) * 256 + k0 + c4 * 4];
            }
            g4 = *(const float4*)&lg[k0 + c4 * 4];
            e4 = *(const float4*)&lb[k0 + c4 * 4];
        }
        // 2 k16 MMAs per 32-k stage; kb in half2 units (8 half2 = 16 halves)
#pragma unroll
        for (int k16 = 0; k16 < 2; k16++) {
            const int kb = k16 * 8;
            unsigned af[4][4], bf[4][2];
#pragma unroll
            for (int mf = 0; mf < 4; mf++) {
                int m = wm * 64 + mf * 16 + g;
                af[mf][0] = Ab[m * 18 + kb + t4];
                af[mf][1] = Ab[(m + 8) * 18 + kb + t4];
                af[mf][2] = Ab[m * 18 + kb + t4 + 4];
                af[mf][3] = Ab[(m + 8) * 18 + kb + t4 + 4];
            }
#pragma unroll
            for (int nf = 0; nf < 4; nf++) {
                int n = wn * 32 + nf * 8 + g;
                bf[nf][0] = Bb[n * 18 + kb + t4];
                bf[nf][1] = Bb[n * 18 + kb + t4 + 4];
            }
#pragma unroll
            for (int mf = 0; mf < 4; mf++)
#pragma unroll
                for (int nf = 0; nf < 4; nf++)
                    mma16h(acc[mf][nf], af[mf], bf[nf]);
        }
        if (st < 7) {
            unsigned* Aw = As + ((st + 1) & 1) * 2304;
            unsigned* Bw = Bs + ((st + 1) & 1) * 2304;
#pragma unroll
            for (int i = 0; i < 4; i++) {
                int row = r0 + 32 * i;
                float2 f01 = __half22float2(*(const __half2*)&ahx[i].x);
                float2 f23 = __half22float2(*(const __half2*)&ahx[i].y);
                unsigned* da = &Aw[row * 18 + c4 * 2];
                da[0] = h2pack((f01.x - mu[i]) * rs[i] * g4.x + e4.x,
                               (f01.y - mu[i]) * rs[i] * g4.y + e4.y);
                da[1] = h2pack((f23.x - mu[i]) * rs[i] * g4.z + e4.z,
                               (f23.y - mu[i]) * rs[i] * g4.w + e4.w);
                unsigned* db = &Bw[row * 18 + c4 * 2];
                db[0] = h2pack(bv[i].x, bv[i].y);
                db[1] = h2pack(bv[i].z, bv[i].w);
            }
            __syncthreads();
        }
    }
    __half* dsth = (n0 < 512) ? g_xmh : g_zh;
    const int nb = (n0 < 512) ? n0 : (n0 - 512);
#pragma unroll
    for (int mf = 0; mf < 4; mf++) {
        int m = m0 + wm * 64 + mf * 16 + g;
#pragma unroll
        for (int nf = 0; nf < 4; nf++) {
            int n = nb + wn * 32 + nf * 8 + 2 * t4;
            *(__half2*)&dsth[m * 512 + n]       = __floats2half2_rn(acc[mf][nf][0], acc[mf][nf][1]);
            *(__half2*)&dsth[(m + 8) * 512 + n] = __floats2half2_rn(acc[mf][nf][2], acc[mf][nf][3]);
        }
    }
}

// =====================================================================
// K5: causal depthwise conv (k=3) + SiLU -> uh fp16 ; {u, silu(z)} fp16
// =====================================================================
__global__ void k_conv4(const float* __restrict__ cw, const float* __restrict__ cb) {
    const int g = blockIdx.x * blockDim.x + threadIdx.x;
    const int base = g * 4;
    const int d = base & 511;
    const int l = (base >> 9) & 4095;
    uint2 h2 = *(const uint2*)&g_xmh[base];
    float2 x2a = __half22float2(*(const __half2*)&h2.x);
    float2 x2b = __half22float2(*(const __half2*)&h2.y);
    float2 x1a = make_float2(0.f, 0.f), x1b = make_float2(0.f, 0.f);
    float2 x0a = make_float2(0.f, 0.f), x0b = make_float2(0.f, 0.f);
    if (l >= 1) {
        uint2 t = *(const uint2*)&g_xmh[base - 512];
        x1a = __half22float2(*(const __half2*)&t.x);
        x1b = __half22float2(*(const __half2*)&t.y);
    }
    if (l >= 2) {
        uint2 t = *(const uint2*)&g_xmh[base - 1024];
        x0a = __half22float2(*(const __half2*)&t.x);
        x0b = __half22float2(*(const __half2*)&t.y);
    }
    float4 w0 = *(const float4*)&cw[d * 3];
    float4 w1 = *(const float4*)&cw[d * 3 + 4];
    float4 w2 = *(const float4*)&cw[d * 3 + 8];
    float4 cb4 = *(const float4*)&cb[d];
    float f[12] = {w0.x, w0.y, w0.z, w0.w, w1.x, w1.y, w1.z, w1.w, w2.x, w2.y, w2.z, w2.w};
    float a0 = x0a.x * f[0] + x1a.x * f[1]  + x2a.x * f[2]  + cb4.x;
    float a1 = x0a.y * f[3] + x1a.y * f[4]  + x2a.y * f[5]  + cb4.y;
    float a2 = x0b.x * f[6] + x1b.x * f[7]  + x2b.x * f[8]  + cb4.z;
    float a3 = x0b.y * f[9] + x1b.y * f[10] + x2b.y * f[11] + cb4.w;
    float u0 = a0 / (1.f + __expf(-a0));
    float u1 = a1 / (1.f + __expf(-a1));
    float u2 = a2 / (1.f + __expf(-a2));
    float u3 = a3 / (1.f + __expf(-a3));
    uint2 uh;
    *(__half2*)&uh.x = __floats2half2_rn(u0, u1);
    *(__half2*)&uh.y = __floats2half2_rn(u2, u3);
    *(uint2*)&g_uh[base] = uh;
    uint2 zh = *(const uint2*)&g_zh[base];
    float2 z01 = __half22float2(*(const __half2*)&zh.x);
    float2 z23 = __half22float2(*(const __half2*)&zh.y);
    uint4 uz;
    *(__half2*)&uz.x = __floats2half2_rn(u0, z01.x / (1.f + __expf(-z01.x)));
    *(__half2*)&uz.y = __floats2half2_rn(u1, z01.y / (1.f + __expf(-z01.y)));
    *(__half2*)&uz.z = __floats2half2_rn(u2, z23.x / (1.f + __expf(-z23.x)));
    *(__half2*)&uz.w = __floats2half2_rn(u3, z23.y / (1.f + __expf(-z23.y)));
    *(uint4*)&g_uz[base] = uz;
}

// =====================================================================
// K6: x_proj GEMM — TF32 TC 128x64 (48 live cols), fp16 A source
// =====================================================================
__global__ void __launch_bounds__(256)
k_xproj_tc(const float* __restrict__ w) {
    __shared__ __align__(16) unsigned As[128 * 36];
    __shared__ __align__(16) unsigned Bs[64 * 36];
    const int m0 = blockIdx.x * 128;
    const int tid = threadIdx.x, lane = tid & 31, wid = tid >> 5;
    const int wm = wid >> 1, wn = wid & 1;
    const int g = lane >> 2, t4 = lane & 3;
    const int r0 = tid >> 3, c4 = tid & 7;
    float acc[2][4][4] = {};
    uint2 ah[4]; float4 bv[2];
#pragma unroll
    for (int i = 0; i < 4; i++)
        ah[i] = *(const uint2*)&g_uh[(m0 + r0 + 32 * i) * 512 + c4 * 4];
#pragma unroll
    for (int i = 0; i < 2; i++) {
        int n = r0 + 32 * i;
        bv[i] = (n < 48) ? *(const float4*)&w[n * 512 + c4 * 4]
                         : make_float4(0.f, 0.f, 0.f, 0.f);
    }
    for (int st = 0; st < 16; st++) {
#pragma unroll
        for (int i = 0; i < 4; i++) {
            float2 f01 = __half22float2(*(const __half2*)&ah[i].x);
            float2 f23 = __half22float2(*(const __half2*)&ah[i].y);
            unsigned* da = &As[(r0 + 32 * i) * 36 + c4 * 4];
            da[0] = tf32c(f01.x); da[1] = tf32c(f01.y);
            da[2] = tf32c(f23.x); da[3] = tf32c(f23.y);
        }
#pragma unroll
        for (int i = 0; i < 2; i++) {
            unsigned* db = &Bs[(r0 + 32 * i) * 36 + c4 * 4];
            db[0] = tf32c(bv[i].x); db[1] = tf32c(bv[i].y);
            db[2] = tf32c(bv[i].z); db[3] = tf32c(bv[i].w);
        }
        __syncthreads();
        if (st < 15) {
            const int k0 = (st + 1) * 32;
#pragma unroll
            for (int i = 0; i < 4; i++)
                ah[i] = *(const uint2*)&g_uh[(m0 + r0 + 32 * i) * 512 + k0 + c4 * 4];
#pragma unroll
            for (int i = 0; i < 2; i++) {
                int n = r0 + 32 * i;
                bv[i] = (n < 48) ? *(const float4*)&w[n * 512 + k0 + c4 * 4]
                                 : make_float4(0.f, 0.f, 0.f, 0.f);
            }
        }
#pragma unroll
        for (int k8 = 0; k8 < 4; k8++) {
            const int kb = k8 * 8;
            unsigned af[2][4], bf[4][2];
#pragma unroll
            for (int mf = 0; mf < 2; mf++) {
                int m = wm * 32 + mf * 16 + g;
                af[mf][0] = As[m * 36 + kb + t4];
                af[mf][1] = As[(m + 8) * 36 + kb + t4];
                af[mf][2] = As[m * 36 + kb + t4 + 4];
                af[mf][3] = As[(m + 8) * 36 + kb + t4 + 4];
            }
#pragma unroll
            for (int nf = 0; nf < 4; nf++) {
                int n = wn * 32 + nf * 8 + g;
                bf[nf][0] = Bs[n * 36 + kb + t4];
                bf[nf][1] = Bs[n * 36 + kb + t4 + 4];
            }
#pragma unroll
            for (int mf = 0; mf < 2; mf++)
#pragma unroll
                for (int nf = 0; nf < 4; nf++)
                    mma8(acc[mf][nf], af[mf], bf[nf]);
        }
        __syncthreads();
    }
    float* bccf = (float*)g_bcc;
#pragma unroll
    for (int mf = 0; mf < 2; mf++) {
#pragma unroll
        for (int nf = 0; nf < 4; nf++) {
#pragma unroll
            for (int half = 0; half < 2; half++) {
                int gm = m0 + wm * 32 + mf * 16 + g + half * 8;
#pragma unroll
                for (int jj = 0; jj < 2; jj++) {
                    int gn = wn * 32 + nf * 8 + 2 * t4 + jj;
                    float v = acc[mf][nf][half * 2 + jj];
                    if (gn < 16)      g_dtin[gm * 16 + gn] = v;
                    else if (gn < 32) bccf[gm * 32 + 2 * (gn - 16)] = v;
                    else if (gn < 48) bccf[gm * 32 + 2 * (gn - 32) + 1] = v;
                }
            }
        }
    }
}

// =====================================================================
// K7: dt_proj GEMM (K=16) + softplus; writes {dt, dt*u} fp16
// =====================================================================
__global__ void k_dtproj(const float* __restrict__ w, const float* __restrict__ dtb) {
    __shared__ float As[16][65];
    __shared__ float Bs[16][65];
    const int m0 = blockIdx.x * 64;
    const int n0 = blockIdx.y * 64;
    const int tid = threadIdx.x;
    const int tx = tid & 15, ty = tid >> 4;
    float acc[4][4] = {};
#pragma unroll
    for (int i = 0; i < 4; i++) {
        int idx = tid + i * 256;
        int m = idx >> 4, kk = idx & 15;
        As[kk][m] = g_dtin[(m0 + m) * 16 + kk];
    }
#pragma unroll
    for (int i = 0; i < 4; i++) {
        int idx = tid + i * 256;
        int n = idx >> 4, kk = idx & 15;
        Bs[kk][n] = w[(n0 + n) * 16 + kk];
    }
    __syncthreads();
#pragma unroll
    for (int kk = 0; kk < 16; kk++) {
        float a[4], c[4];
#pragma unroll
        for (int i = 0; i < 4; i++) a[i] = As[kk][ty * 4 + i];
#pragma unroll
        for (int j = 0; j < 4; j++) c[j] = Bs[kk][tx * 4 + j];
#pragma unroll
        for (int i = 0; i < 4; i++)
#pragma unroll
            for (int j = 0; j < 4; j++) acc[i][j] += a[i] * c[j];
    }
#pragma unroll
    for (int i = 0; i < 4; i++) {
        int gm = m0 + ty * 4 + i;
        uint2 uh = *(const uint2*)&g_uh[gm * 512 + n0 + tx * 4];
        float2 u01 = __half22float2(*(const __half2*)&uh.x);
        float2 u23 = __half22float2(*(const __half2*)&uh.y);
        float um[4] = {u01.x, u01.y, u23.x, u23.y};
#pragma unroll
        for (int j = 0; j < 4; j++) {
            int gn = n0 + tx * 4 + j;
            float x = acc[i][j] + dtb[gn];
            float sp = (x > 20.f) ? x : log1pf(__expf(x));
            g_a[gm * 512 + gn] = __floats2half2_rn(sp, sp * um[j]);
        }
    }
}

// =====================================================================
// K8: scan pass 1 — warp = 4 channels x 8 lanes x 2 states/lane
// =====================================================================
__global__ void __launch_bounds__(256)
k_scan1(const float* __restrict__ alog) {
    const int w    = (blockIdx.x * blockDim.x + threadIdx.x) >> 5;
    const int lane = threadIdx.x & 31;
    const int chunk = w & (NCH - 1);
    const int dq   = (w >> 5) & 127;
    const int b    = w >> 12;
    const int c2 = lane >> 3, s8 = lane & 7;
    const int d  = dq * 4 + c2;
    const int s0 = 2 * s8;
    const float An2a = -__expf(alog[d * 16 + s0])     * LOG2E;
    const float An2b = -__expf(alog[d * 16 + s0 + 1]) * LOG2E;
    float2 h = make_float2(0.f, 0.f);
    float2 P = make_float2(1.f, 1.f);
    const int l0 = chunk * CT_;
    const __half2* ap = g_a + (size_t)(b * LL + l0) * 512 + d;
    const float4*  bp = (const float4*)(g_bcc + (size_t)(b * LL + l0) * 16) + s8;
#pragma unroll 8
    for (int t = 0; t < CT_; t++) {
        float2 av = __half22float2(ap[t * 512]);
        float4 bc = bp[t * 8];
        float dAa = exp2f(av.x * An2a);
        float dAb = exp2f(av.x * An2b);
        h.x = fmaf(dAa, h.x, av.y * bc.x);
        h.y = fmaf(dAb, h.y, av.y * bc.z);
        P.x *= dAa; P.y *= dAb;
    }
    const int tI = (b * 512 + d) * 16 + s0;
    *(float2*)&g_P[chunk * TT_ + tI]  = P;
    *(float2*)&g_Hc[chunk * TT_ + tI] = h;
}

// =====================================================================
// K9: chunk combine — materialize prefix states (coalesced float2)
// =====================================================================
__global__ void k_comb() {
    const int tI = (blockIdx.x * blockDim.x + threadIdx.x) * 2;  // TT_/2 threads
    float2 h = make_float2(0.f, 0.f);
    for (int c = 0; c < NCH; c++) {
        *(float2*)&g_hini[c * TT_ + tI] = h;
        float2 Pv = *(const float2*)&g_P[c * TT_ + tI];
        float2 Hv = *(const float2*)&g_Hc[c * TT_ + tI];
        h.x = Pv.x * h.x + Hv.x;
        h.y = Pv.y * h.y + Hv.y;
    }
}

// =====================================================================
// K10: scan pass 2 — load prefix, replay, y (fp16 out)
// =====================================================================
__global__ void __launch_bounds__(256)
k_scan2(const float* __restrict__ alog, const float* __restrict__ Dp) {
    const int w    = (blockIdx.x * blockDim.x + threadIdx.x) >> 5;
    const int lane = threadIdx.x & 31;
    const int chunk = w & (NCH - 1);
    const int dq   = (w >> 5) & 127;
    const int b    = w >> 12;
    const int c2 = lane >> 3, s8 = lane & 7;
    const int d  = dq * 4 + c2;
    const int s0 = 2 * s8;
    const float An2a = -__expf(alog[d * 16 + s0])     * LOG2E;
    const float An2b = -__expf(alog[d * 16 + s0 + 1]) * LOG2E;
    const float Dv = Dp[d];
    const int tI = (b * 512 + d) * 16 + s0;
    float2 h = *(const float2*)&g_hini[chunk * TT_ + tI];
    const int l0 = chunk * CT_;
    const __half2* ap = g_a  + (size_t)(b * LL + l0) * 512 + d;
    const float4*  bp = (const float4*)(g_bcc + (size_t)(b * LL + l0) * 16) + s8;
    const __half2* up = g_uz + (size_t)(b * LL + l0) * 512 + d;
    __half* yp = g_yfin + (size_t)(b * LL + l0) * 512 + d;
#pragma unroll 4
    for (int t = 0; t < CT_; t++) {
        float2 av = __half22float2(ap[t * 512]);
        float4 bc = bp[t * 8];
        float dAa = exp2f(av.x * An2a);
        float dAb = exp2f(av.x * An2b);
        h.x = fmaf(dAa, h.x, av.y * bc.x);
        h.y = fmaf(dAb, h.y, av.y * bc.z);
        float part = h.x * bc.y + h.y * bc.w;
        part += __shfl_xor_sync(0xffffffffu, part, 1);
        part += __shfl_xor_sync(0xffffffffu, part, 2);
        part += __shfl_xor_sync(0xffffffffu, part, 4);
        if (s8 == 0) {
            float2 uzv = __half22float2(up[t * 512]);
            yp[t * 512] = __float2half((part + uzv.x * Dv) * uzv.y);
        }
    }
}

// =====================================================================
// K11: out_proj GEMM — TF32 TC, fp16 A source, double-buffered,
//      residual + NCHW scatter
// =====================================================================
__global__ void __launch_bounds__(256)
k_outproj_tc(const float* __restrict__ w, float* __restrict__ out) {
    extern __shared__ unsigned dyn[];
    unsigned* As = dyn;
    unsigned* Bs = dyn + 2 * 4608;
    const int m0 = blockIdx.x * 128, n0 = blockIdx.y * 128;
    const int tid = threadIdx.x, lane = tid & 31, wid = tid >> 5;
    const int wm = wid >> 2, wn = wid & 3;
    const int g = lane >> 2, t4 = lane & 3;
    const int r0 = tid >> 3, c4 = tid & 7;
    float acc[4][4][4] = {};
    uint2 ah[4]; float4 bv[4];
#pragma unroll
    for (int i = 0; i < 4; i++) {
        ah[i] = *(const uint2*)&g_yfin[(m0 + r0 + 32 * i) * 512 + c4 * 4];
        bv[i] = *(const float4*)&w[(n0 + r0 + 32 * i) * 512 + c4 * 4];
    }
#pragma unroll
    for (int i = 0; i < 4; i++) {
        int row = r0 + 32 * i;
        float2 f01 = __half22float2(*(const __half2*)&ah[i].x);
        float2 f23 = __half22float2(*(const __half2*)&ah[i].y);
        unsigned* da = &As[row * 36 + c4 * 4];
        da[0] = tf32c(f01.x); da[1] = tf32c(f01.y);
        da[2] = tf32c(f23.x); da[3] = tf32c(f23.y);
        unsigned* db = &Bs[row * 36 + c4 * 4];
        db[0] = tf32c(bv[i].x); db[1] = tf32c(bv[i].y);
        db[2] = tf32c(bv[i].z); db[3] = tf32c(bv[i].w);
    }
    __syncthreads();
    for (int st = 0; st < 16; st++) {
        const unsigned* Ab = As + (st & 1) * 4608;
        const unsigned* Bb = Bs + (st & 1) * 4608;
        if (st < 15) {
            const int k0 = (st + 1) * 32;
#pragma unroll
            for (int i = 0; i < 4; i++) {
                ah[i] = *(const uint2*)&g_yfin[(m0 + r0 + 32 * i) * 512 + k0 + c4 * 4];
                bv[i] = *(const float4*)&w[(n0 + r0 + 32 * i) * 512 + k0 + c4 * 4];
            }
        }
#pragma unroll
        for (int k8 = 0; k8 < 4; k8++) {
            const int kb = k8 * 8;
            unsigned af[4][4], bf[4][2];
#pragma unroll
            for (int mf = 0; mf < 4; mf++) {
                int m = wm * 64 + mf * 16 + g;
                af[mf][0] = Ab[m * 36 + kb + t4];
                af[mf][1] = Ab[(m + 8) * 36 + kb + t4];
                af[mf][2] = Ab[m * 36 + kb + t4 + 4];
                af[mf][3] = Ab[(m + 8) * 36 + kb + t4 + 4];
            }
#pragma unroll
            for (int nf = 0; nf < 4; nf++) {
                int n = wn * 32 + nf * 8 + g;
                bf[nf][0] = Bb[n * 36 + kb + t4];
                bf[nf][1] = Bb[n * 36 + kb + t4 + 4];
            }
#pragma unroll
            for (int mf = 0; mf < 4; mf++)
#pragma unroll
                for (int nf = 0; nf < 4; nf++)
                    mma8(acc[mf][nf], af[mf], bf[nf]);
        }
        if (st < 15) {
            unsigned* Aw = As + ((st + 1) & 1) * 4608;
            unsigned* Bw = Bs + ((st + 1) & 1) * 4608;
#pragma unroll
            for (int i = 0; i < 4; i++) {
                int row = r0 + 32 * i;
                float2 f01 = __half22float2(*(const __half2*)&ah[i].x);
                float2 f23 = __half22float2(*(const __half2*)&ah[i].y);
                unsigned* da = &Aw[row * 36 + c4 * 4];
                da[0] = tf32c(f01.x); da[1] = tf32c(f01.y);
                da[2] = tf32c(f23.x); da[3] = tf32c(f23.y);
                unsigned* db = &Bw[row * 36 + c4 * 4];
                db[0] = tf32c(bv[i].x); db[1] = tf32c(bv[i].y);
                db[2] = tf32c(bv[i].z); db[3] = tf32c(bv[i].w);
            }
            __syncthreads();
        }
    }
    const int bb = m0 >> 12;
#pragma unroll
    for (int mf = 0; mf < 4; mf++) {
        int m = m0 + wm * 64 + mf * 16 + g;
        int l = m & 4095;
#pragma unroll
        for (int nf = 0; nf < 4; nf++) {
            int n = n0 + wn * 32 + nf * 8 + 2 * t4;
            size_t i0 = (size_t)(bb * 256 + n) * 4096 + l;
            size_t i1 = i0 + 4096;
            out[i0]     = acc[mf][nf][0] + g_fused[i0];
            out[i1]     = acc[mf][nf][1] + g_fused[i1];
            out[i0 + 8] = acc[mf][nf][2] + g_fused[i0 + 8];
            out[i1 + 8] = acc[mf][nf][3] + g_fused[i1 + 8];
        }
    }
}

// =====================================================================
extern "C" void kernel_launch(void* const* d_in, const int* in_sizes, int n_in,
                              void* d_out, int out_size) {
    const float* resnet = (const float*)d_in[0];
    const float* scp    = (const float*)d_in[1];
    const float* scpw   = (const float*)d_in[2];
    const float* sg = (const float*)d_in[3];
    const float* sb = (const float*)d_in[4];
    const float* sm = (const float*)d_in[5];
    const float* sv = (const float*)d_in[6];
    const float* rg = (const float*)d_in[7];
    const float* rb = (const float*)d_in[8];
    const float* rm = (const float*)d_in[9];
    const float* rv = (const float*)d_in[10];
    const float* lg = (const float*)d_in[11];
    const float* lb = (const float*)d_in[12];
    const float* inw = (const float*)d_in[13];
    const float* cw  = (const float*)d_in[14];
    const float* cb  = (const float*)d_in[15];
    const float* xw  = (const float*)d_in[16];
    const float* dtw = (const float*)d_in[17];
    const float* dtb = (const float*)d_in[18];
    const float* alog = (const float*)d_in[19];
    const float* Dp   = (const float*)d_in[20];
    const float* ow   = (const float*)d_in[21];
    float* out = (float*)d_out;

    const int DYN  = 4 * 4608 * 4;   // outproj (tf32 double-buffered)
    const int DYNH = 4 * 2304 * 4;   // inproj  (fp16 double-buffered) = 36864
    cudaFuncSetAttribute(k_inproj_tc, cudaFuncAttributeMaxDynamicSharedMemorySize, DYNH);
    cudaFuncSetAttribute(k_outproj_tc, cudaFuncAttributeMaxDynamicSharedMemorySize, DYN);

    k_scp_tc   <<<dim3(2, 8, 2), 256>>>(scp, scpw, sg, sb, sm, sv);
    k_fuse     <<<dim3(128, 8, 2), dim3(32, 8)>>>(resnet, rg, rb, rm, rv);
    k_inproj_tc<<<dim3(64, 8), 256, DYNH>>>(inw, lg, lb);
    k_conv4    <<<(NB * LL * DI_) / 1024, 256>>>(cw, cb);
    k_xproj_tc <<<64, 256>>>(xw);
    k_dtproj   <<<dim3(128, 8), 256>>>(dtw, dtb);
    k_scan1    <<<1024, 256>>>(alog);
    k_comb     <<<32, 256>>>();
    k_scan2    <<<1024, 256>>>(alog, Dp);
    k_outproj_tc<<<dim3(64, 2), 256, DYN>>>(ow, out);
}